// round 3
// baseline (speedup 1.0000x reference)
#include <cuda_runtime.h>
#include <cuda_bf16.h>

// ---------------------------------------------------------------------------
// LPKT: 99-step recurrence over B=64 independent sequences.
// Prep kernels hoist all non-recurrent linear algebra; one persistent CTA per
// batch element runs the scan with all state in SMEM; epilogue computes y.
// ---------------------------------------------------------------------------

typedef unsigned long long u64;

#define NB 64
#define NS 100
#define NQ 129   // N_Q + 1
#define DD 128

// -------------------- device scratch (no allocation allowed) ---------------
__device__ __align__(16) float g_AL [NB*NS*DD];    // all_learning
__device__ __align__(16) float g_G23[NB*NS*2*DD];  // feat[0:384]@[W2|W3] + b
__device__ __align__(16) float g_UIT[NB*NS*DD];    // it@W4i + b4
__device__ __align__(16) float g_HT [NB*NS*DD];    // h_tilde per (b,t)
__device__ __align__(16) float g_W23T[2*DD*DD];    // [j][k]: W2r/W3r transposed
__device__ __align__(16) float g_W5T [DD*2*DD];    // [f][k]: W5 transposed
__device__ __align__(16) float g_w1s [DD];         // colsum W1[256:384]
__device__ __align__(16) float g_QS  [NB*NS];      // sum of q row per (b,t)

__device__ __forceinline__ float sigm(float x) {
    return __fdividef(1.f, 1.f + __expf(-x));
}

#define FMA2(d, a, bb) asm("fma.rn.f32x2 %0, %1, %2, %0;" : "+l"(d) : "l"(a), "l"(bb))

__device__ __forceinline__ float2 unpk(u64 v) {
    float2 r;
    asm("mov.b64 {%0, %1}, %2;" : "=f"(r.x), "=f"(r.y) : "l"(v));
    return r;
}

// ============================================================================
// prep_misc: W23T (transpose of W2[384:512] | W3[384:512]), W5T, w1sum
// ============================================================================
__global__ void prep_misc(const float* __restrict__ W1, const float* __restrict__ W2,
                          const float* __restrict__ W3, const float* __restrict__ W5)
{
    for (int idx = blockIdx.x*blockDim.x + threadIdx.x; idx < 65536 + 128;
         idx += gridDim.x*blockDim.x) {
        if (idx < 32768) {
            int j = idx >> 7, k = idx & 127;
            g_W23T[idx] = (j < 128) ? W2[(384+k)*128 + j] : W3[(384+k)*128 + (j-128)];
        } else if (idx < 65536) {
            int r = idx - 32768;
            int f = r >> 8, k = r & 255;
            g_W5T[r] = W5[k*128 + f];
        } else {
            int f = idx - 65536;
            float s = 0.f;
            for (int k = 0; k < 128; k++) s += W1[(256+k)*128 + f];
            g_w1s[f] = s;
        }
    }
}

// ============================================================================
// prep_qs: row sums of q_matrix gathered by e_data
// ============================================================================
__global__ void prep_qs(const int* __restrict__ e_data, const float* __restrict__ q_matrix)
{
    int b = blockIdx.x, t = threadIdx.x;
    if (t < NS) {
        int e = e_data[b*NS + t];
        const float* q = q_matrix + (long)e * NQ;
        float s = 0.f;
        for (int i = 0; i < NQ; i++) s += q[i];
        g_QS[b*NS + t] = s;
    }
}

// ============================================================================
// prep_AL: all_learning[b,s,:] = [e_emb, at_emb, a] @ W1 + b1
// grid (64,13), 128 threads
// ============================================================================
__global__ void __launch_bounds__(128) prep_AL(
    const int* __restrict__ e_data, const int* __restrict__ a_data,
    const int* __restrict__ at_data,
    const float* __restrict__ E_e, const float* __restrict__ E_at,
    const float* __restrict__ W1, const float* __restrict__ b1)
{
    int b = blockIdx.x, s0 = blockIdx.y*8, f = threadIdx.x;
    __shared__ float se[8][128], sa[8][128], av[8];
    int cnt = min(8, NS - s0);
    for (int t = 0; t < 8; t++) {
        if (t < cnt) {
            int s = s0 + t;
            int e  = e_data [b*NS + s];
            int at = at_data[b*NS + s];
            se[t][f] = E_e [e *128 + f];
            sa[t][f] = E_at[at*128 + f];
            if (f == 0) av[t] = (float)a_data[b*NS + s];
        } else { se[t][f] = 0.f; sa[t][f] = 0.f; if (f == 0) av[t] = 0.f; }
    }
    __syncthreads();
    float w1sf = g_w1s[f], b1f = b1[f];
    float acc[8];
#pragma unroll
    for (int t = 0; t < 8; t++) acc[t] = b1f + av[t]*w1sf;
    for (int k = 0; k < 128; k++) {
        float w = W1[k*128 + f];
#pragma unroll
        for (int t = 0; t < 8; t++) acc[t] += se[t][k]*w;
    }
    for (int k = 0; k < 128; k++) {
        float w = W1[(128+k)*128 + f];
#pragma unroll
        for (int t = 0; t < 8; t++) acc[t] += sa[t][k]*w;
    }
    for (int t = 0; t < cnt; t++) g_AL[(b*NS + s0 + t)*128 + f] = acc[t];
}

// ============================================================================
// prep_UIT: it_emb @ W4i + b4
// ============================================================================
__global__ void __launch_bounds__(128) prep_UIT(
    const int* __restrict__ it_data, const float* __restrict__ E_it,
    const float* __restrict__ W4, const float* __restrict__ b4)
{
    int b = blockIdx.x, s0 = blockIdx.y*8, f = threadIdx.x;
    __shared__ float si[8][128];
    int cnt = min(8, NS - s0);
    for (int t = 0; t < 8; t++) {
        if (t < cnt) { int it = it_data[b*NS + s0 + t]; si[t][f] = E_it[it*128 + f]; }
        else si[t][f] = 0.f;
    }
    __syncthreads();
    float bf = b4[f];
    float acc[8];
#pragma unroll
    for (int t = 0; t < 8; t++) acc[t] = bf;
    for (int k = 0; k < 128; k++) {
        float wv = W4[(256+k)*128 + f];
#pragma unroll
        for (int t = 0; t < 8; t++) acc[t] += si[t][k]*wv;
    }
    for (int t = 0; t < cnt; t++) g_UIT[(b*NS + s0 + t)*128 + f] = acc[t];
}

// ============================================================================
// prep_G23: feat3 = [AL[t-1], it_emb[t], AL[t]] (384) -> @W2[0:384]+b2 | @W3+b3
// grid (64,10), 256 threads, 10 t per block
// ============================================================================
__global__ void __launch_bounds__(256) prep_G23(
    const int* __restrict__ it_data, const float* __restrict__ E_it,
    const float* __restrict__ W2, const float* __restrict__ b2,
    const float* __restrict__ W3, const float* __restrict__ b3)
{
    int b = blockIdx.x, t0 = blockIdx.y*10;
    int T = min(10, 99 - t0);
    __shared__ float sf[10][384];
    for (int idx = threadIdx.x; idx < T*384; idx += 256) {
        int tt = idx / 384, kk = idx - tt*384;
        int t = t0 + tt;
        float v;
        if (kk < 128)       v = (t == 0) ? 0.f : g_AL[(b*NS + t - 1)*128 + kk];
        else if (kk < 256) { int it = it_data[b*NS + t]; v = E_it[it*128 + (kk-128)]; }
        else                v = g_AL[(b*NS + t)*128 + (kk-256)];
        sf[tt][kk] = v;
    }
    __syncthreads();
    int j = threadIdx.x;
    const float* Wc;
    float bias;
    if (j < 128) { Wc = W2 + j;        bias = b2[j];     }
    else         { Wc = W3 + (j-128);  bias = b3[j-128]; }
    float acc[10];
#pragma unroll
    for (int tt = 0; tt < 10; tt++) acc[tt] = bias;
    for (int k = 0; k < 384; k++) {
        float wv = Wc[k*128];
#pragma unroll
        for (int tt = 0; tt < 10; tt++) acc[tt] += sf[tt][k]*wv;
    }
    for (int tt = 0; tt < T; tt++) g_G23[(b*NS + t0 + tt)*256 + j] = acc[tt];
}

// ============================================================================
// Main persistent scan kernel: one CTA per b, 512 threads.
// SMEM: h[129][128], W4h (k-pair interleaved), W4l, plus small vectors.
// ============================================================================
template<int NR>
__device__ __forceinline__ void gemm_update(
    int r0, int c0, int lane, float* sh, const float* sW4h,
    const float* sQE, const float* sQN, float4 LG4, float4 C4,
    float& htp0, float& htp1, float& htp2, float& htp3)
{
    u64 acc[NR][4];
#pragma unroll
    for (int j = 0; j < NR; j++) { acc[j][0]=0ull; acc[j][1]=0ull; acc[j][2]=0ull; acc[j][3]=0ull; }
    const u64* Wp = (const u64*)sW4h;   // [k2][128] pairs
    const u64* Hp = (const u64*)sh;     // [r][64]   pairs
    int reff[NR];
#pragma unroll
    for (int j = 0; j < NR; j++) reff[j] = min(r0 + j, 128) * 64;
#pragma unroll 4
    for (int k2 = 0; k2 < 64; k2++) {
        const u64* wrow = Wp + k2*128 + c0;
        u64 w0 = wrow[0], w1 = wrow[1], w2 = wrow[2], w3 = wrow[3];
#pragma unroll
        for (int j = 0; j < NR; j++) {
            u64 hp = Hp[reff[j] + k2];
            FMA2(acc[j][0], hp, w0);
            FMA2(acc[j][1], hp, w1);
            FMA2(acc[j][2], hp, w2);
            FMA2(acc[j][3], hp, w3);
        }
    }
#pragma unroll
    for (int j = 0; j < NR; j++) {
        int r = r0 + j;
        if (r < 129) {                              // warp-uniform
            float2 a0 = unpk(acc[j][0]), a1 = unpk(acc[j][1]);
            float2 a2 = unpk(acc[j][2]), a3 = unpk(acc[j][3]);
            float g0 = a0.x + a0.y + C4.x;
            float g1 = a1.x + a1.y + C4.y;
            float g2 = a2.x + a2.y + C4.z;
            float g3 = a3.x + a3.y + C4.w;
            float gm0 = sigm(g0), gm1 = sigm(g1), gm2 = sigm(g2), gm3 = sigm(g3);
            float4 hold = ((const float4*)sh)[r*32 + lane];
            float qe = sQE[r], qn = sQN[r];
            float4 hn;
            hn.x = qe*LG4.x + gm0*hold.x;
            hn.y = qe*LG4.y + gm1*hold.y;
            hn.z = qe*LG4.z + gm2*hold.z;
            hn.w = qe*LG4.w + gm3*hold.w;
            ((float4*)sh)[r*32 + lane] = hn;
            htp0 += qn*hn.x; htp1 += qn*hn.y; htp2 += qn*hn.z; htp3 += qn*hn.w;
        }
    }
}

__global__ void __launch_bounds__(512, 1) lpkt_main(
    const int* __restrict__ e_data, const float* __restrict__ q_matrix,
    const float* __restrict__ h0, const float* __restrict__ W4)
{
    extern __shared__ float sm[];
    float* sh    = sm;                // 16512
    float* sW4h  = sm   + 16512;      // 16384 (k-pair interleaved)
    float* sW4l  = sW4h + 16384;      // 16384 [k][f]
    float* sLG   = sW4l + 16384;      // 128
    float* sC    = sLG  + 128;        // 128
    float* sHT   = sC   + 128;        // 128
    float* sQ    = sHT  + 128;        // 2*132
    float* sPart = sQ   + 264;        // 16*128
    float* sG    = sPart+ 2048;       // 256
    float* sCp   = sG   + 256;        // 512

    const int b = blockIdx.x, tid = threadIdx.x;
    const int w = tid >> 5, lane = tid & 31;
    const int c0 = lane << 2;

    // ---- init: load weights + h0 + q row 0 ----
    for (int idx = tid; idx < 16384; idx += 512) {
        int k = idx >> 7, c = idx & 127;
        sW4h[(k >> 1)*256 + 2*c + (k & 1)] = W4[idx];        // pair layout
        sW4l[idx] = W4[16384 + idx];
    }
    for (int idx = tid; idx < 16512; idx += 512) sh[idx] = h0[idx];
    {
        int e0 = e_data[b*NS];
        if (tid < NQ) sQ[tid] = q_matrix[(long)e0*NQ + tid];
    }
    __syncthreads();

    // ---- ht0 = (q0 @ h0) / sum(q0) ----
    {
        int f = tid & 127, ch = tid >> 7;
        float acc = 0.f;
        int r0 = ch*33, r1 = min(r0 + 33, 129);
        for (int r = r0; r < r1; r++) acc += sQ[r]*sh[r*128 + f];
        sCp[tid] = acc;
    }
    __syncthreads();
    if (tid < 128) {
        float qs0 = g_QS[b*NS];
        sHT[tid] = __fdividef(sCp[tid] + sCp[128+tid] + sCp[256+tid] + sCp[384+tid], qs0);
    }
    __syncthreads();

    const int rbase = w*9;

    for (int t = 0; t < 99; t++) {
        const float* sQE = sQ + (t & 1)*132;
        float*       sQN = sQ + ((t + 1) & 1)*132;

        // ---- (A) load q_next row; W23T GEMV on h_tilde; UIT prefetch ----
        float ureg = 0.f;
        if (tid < 128) ureg = g_UIT[(b*NS + t)*128 + tid];
        {
            int en = e_data[b*NS + t + 1];
            if (tid < NQ) sQN[tid] = q_matrix[(long)en*NQ + tid];
        }
        {
            float4 hv = ((const float4*)sHT)[lane];
            const float* gbase = g_G23 + (b*NS + t)*256;
#pragma unroll
            for (int i = 0; i < 16; i++) {
                int j = w*16 + i;
                float4 wv = ((const float4*)(g_W23T + j*128))[lane];
                float v = hv.x*wv.x + hv.y*wv.y + hv.z*wv.z + hv.w*wv.w;
                v += __shfl_xor_sync(0xffffffffu, v, 16);
                v += __shfl_xor_sync(0xffffffffu, v, 8);
                v += __shfl_xor_sync(0xffffffffu, v, 4);
                v += __shfl_xor_sync(0xffffffffu, v, 2);
                v += __shfl_xor_sync(0xffffffffu, v, 1);
                if (lane == 0) sG[j] = v + gbase[j];
            }
        }
        __syncthreads();

        // ---- (B) LG = sigmoid(g3) * sigmoid(2*g2)   [(tanh+1)/2 == sigm(2x)]
        if (tid < 128) {
            float g2 = sG[tid], g3 = sG[128 + tid];
            sLG[tid] = sigm(g3) * sigm(2.f*g2);
        }
        __syncthreads();

        // ---- (C) c = LG @ W4l + UIT ----
        {
            int f = tid & 127, ch = tid >> 7;
            float acc = 0.f;
            int k0 = ch*32;
#pragma unroll 8
            for (int kk = 0; kk < 32; kk++) {
                int k = k0 + kk;
                acc += sLG[k]*sW4l[k*128 + f];
            }
            sCp[tid] = acc;
        }
        __syncthreads();
        if (tid < 128) sC[tid] = ureg + sCp[tid] + sCp[128+tid] + sCp[256+tid] + sCp[384+tid];
        __syncthreads();

        // ---- (D) h = q_e (x) LG + sigmoid(h@W4h + c) * h ; partial h_tilde ----
        {
            float4 LG4 = ((const float4*)sLG)[lane];
            float4 C4  = ((const float4*)sC)[lane];
            float htp0 = 0.f, htp1 = 0.f, htp2 = 0.f, htp3 = 0.f;
            gemm_update<5>(rbase,     c0, lane, sh, sW4h, sQE, sQN, LG4, C4, htp0, htp1, htp2, htp3);
            gemm_update<4>(rbase + 5, c0, lane, sh, sW4h, sQE, sQN, LG4, C4, htp0, htp1, htp2, htp3);
            float4 hp; hp.x = htp0; hp.y = htp1; hp.z = htp2; hp.w = htp3;
            ((float4*)(sPart + w*128))[lane] = hp;
        }
        __syncthreads();

        // ---- (E) reduce h_tilde; store; roll ----
        if (tid < 128) {
            float s = 0.f;
#pragma unroll
            for (int ww = 0; ww < 16; ww++) s += sPart[ww*128 + tid];
            float qs = g_QS[b*NS + t + 1];
            float v = __fdividef(s, qs);
            sHT[tid] = v;
            g_HT[(b*NS + t)*128 + tid] = v;
        }
        __syncthreads();
    }
}

// ============================================================================
// Epilogue: pred[b, t+1] = mean_f sigmoid([e_next, h_tilde] @ W5 + b5)
// grid (64,9), 128 threads, 11 t per block (L1 keeps W5T resident)
// ============================================================================
__global__ void __launch_bounds__(128) lpkt_epi(
    const int* __restrict__ e_data, const float* __restrict__ E_e,
    const float* __restrict__ b5, float* __restrict__ pred)
{
    int b = blockIdx.x, f = threadIdx.x;
    __shared__ float sx[256];
    __shared__ float sr[4];
    float b5f = b5[f];
    if (blockIdx.y == 0 && f == 0) pred[b*NS] = 0.f;
    for (int tt = 0; tt < 11; tt++) {
        int t = blockIdx.y*11 + tt;          // 9*11 = 99, t in [0,98]
        int en = e_data[b*NS + t + 1];
        __syncthreads();
        sx[f]       = E_e[en*128 + f];
        sx[128 + f] = g_HT[(b*NS + t)*128 + f];
        __syncthreads();
        float acc = b5f;
        const float4* wp = (const float4*)(g_W5T + f*256);
        const float4* xp = (const float4*)sx;
#pragma unroll 8
        for (int k4 = 0; k4 < 64; k4++) {
            float4 wv = wp[k4], xv = xp[k4];
            acc += wv.x*xv.x + wv.y*xv.y + wv.z*xv.z + wv.w*xv.w;
        }
        float v = sigm(acc);
        v += __shfl_xor_sync(0xffffffffu, v, 16);
        v += __shfl_xor_sync(0xffffffffu, v, 8);
        v += __shfl_xor_sync(0xffffffffu, v, 4);
        v += __shfl_xor_sync(0xffffffffu, v, 2);
        v += __shfl_xor_sync(0xffffffffu, v, 1);
        if ((f & 31) == 0) sr[f >> 5] = v;
        __syncthreads();
        if (f == 0) pred[b*NS + t + 1] = (sr[0] + sr[1] + sr[2] + sr[3]) * (1.f/128.f);
    }
}

// ============================================================================
// launch
// ============================================================================
extern "C" void kernel_launch(void* const* d_in, const int* in_sizes, int n_in,
                              void* d_out, int out_size)
{
    const int*   e_data   = (const int*)  d_in[0];
    const int*   a_data   = (const int*)  d_in[1];
    const int*   it_data  = (const int*)  d_in[2];
    const int*   at_data  = (const int*)  d_in[3];
    const float* q_matrix = (const float*)d_in[4];
    const float* h0       = (const float*)d_in[5];
    const float* E_e      = (const float*)d_in[6];
    const float* E_at     = (const float*)d_in[7];
    const float* E_it     = (const float*)d_in[8];
    const float* W1       = (const float*)d_in[9];
    const float* b1       = (const float*)d_in[10];
    const float* W2       = (const float*)d_in[11];
    const float* b2       = (const float*)d_in[12];
    const float* W3       = (const float*)d_in[13];
    const float* b3       = (const float*)d_in[14];
    const float* W4       = (const float*)d_in[15];
    const float* b4       = (const float*)d_in[16];
    const float* W5       = (const float*)d_in[17];
    const float* b5       = (const float*)d_in[18];
    float* pred = (float*)d_out;

    const int SMEM_MAIN = 52744 * 4;   // 210,976 B
    cudaFuncSetAttribute(lpkt_main, cudaFuncAttributeMaxDynamicSharedMemorySize, SMEM_MAIN);

    prep_misc<<<128, 512>>>(W1, W2, W3, W5);
    prep_qs<<<64, 128>>>(e_data, q_matrix);
    prep_AL<<<dim3(64, 13), 128>>>(e_data, a_data, at_data, E_e, E_at, W1, b1);
    prep_UIT<<<dim3(64, 13), 128>>>(it_data, E_it, W4, b4);
    prep_G23<<<dim3(64, 10), 256>>>(it_data, E_it, W2, b2, W3, b3);
    lpkt_main<<<64, 512, SMEM_MAIN>>>(e_data, q_matrix, h0, W4);
    lpkt_epi<<<dim3(64, 9), 128>>>(e_data, E_e, b5, pred);
}

// round 4
// speedup vs baseline: 1.4212x; 1.4212x over previous
#include <cuda_runtime.h>
#include <cuda_bf16.h>

// ---------------------------------------------------------------------------
// LPKT: 99-step recurrence over B=64 independent sequences.
// Prep kernels hoist all non-recurrent linear algebra; one persistent CTA per
// batch element runs the scan with all state in SMEM; epilogue computes y.
// ---------------------------------------------------------------------------

typedef unsigned long long u64;

#define NB 64
#define NS 100
#define NQ 129   // N_Q + 1
#define DD 128

// -------------------- device scratch (no allocation allowed) ---------------
__device__ __align__(16) float g_AL [NB*NS*DD];    // all_learning
__device__ __align__(16) float g_G23[NB*NS*2*DD];  // feat[0:384]@[W2|W3] + b
__device__ __align__(16) float g_UIT[NB*NS*DD];    // it@W4i + b4
__device__ __align__(16) float g_HT [NB*NS*DD];    // h_tilde per (b,t)
__device__ __align__(16) float g_W23T[2*DD*DD];    // [j][k]: W2r/W3r transposed
__device__ __align__(16) float g_W5T [DD*2*DD];    // [f][k]: W5 transposed
__device__ __align__(16) float g_w1s [DD];         // colsum W1[256:384]
__device__ __align__(16) float g_QS  [NB*NS];      // sum of q row per (b,t)

__device__ __forceinline__ float sigm(float x) {
    return __fdividef(1.f, 1.f + __expf(-x));
}

#define FMA2(d, a, bb) asm("fma.rn.f32x2 %0, %1, %2, %0;" : "+l"(d) : "l"(a), "l"(bb))

__device__ __forceinline__ float2 unpk(u64 v) {
    float2 r;
    asm("mov.b64 {%0, %1}, %2;" : "=f"(r.x), "=f"(r.y) : "l"(v));
    return r;
}

// ============================================================================
// prep_misc: W23T (transpose of W2[384:512] | W3[384:512]), W5T, w1sum
// ============================================================================
__global__ void prep_misc(const float* __restrict__ W1, const float* __restrict__ W2,
                          const float* __restrict__ W3, const float* __restrict__ W5)
{
    for (int idx = blockIdx.x*blockDim.x + threadIdx.x; idx < 65536 + 128;
         idx += gridDim.x*blockDim.x) {
        if (idx < 32768) {
            int j = idx >> 7, k = idx & 127;
            g_W23T[idx] = (j < 128) ? W2[(384+k)*128 + j] : W3[(384+k)*128 + (j-128)];
        } else if (idx < 65536) {
            int r = idx - 32768;
            int f = r >> 8, k = r & 255;
            g_W5T[r] = W5[k*128 + f];
        } else {
            int f = idx - 65536;
            float s = 0.f;
            for (int k = 0; k < 128; k++) s += W1[(256+k)*128 + f];
            g_w1s[f] = s;
        }
    }
}

// ============================================================================
// prep_qs: row sums of q_matrix gathered by e_data
// ============================================================================
__global__ void prep_qs(const int* __restrict__ e_data, const float* __restrict__ q_matrix)
{
    int b = blockIdx.x, t = threadIdx.x;
    if (t < NS) {
        int e = e_data[b*NS + t];
        const float* q = q_matrix + (long)e * NQ;
        float s = 0.f;
        for (int i = 0; i < NQ; i++) s += q[i];
        g_QS[b*NS + t] = s;
    }
}

// ============================================================================
// prep_AL: all_learning[b,s,:] = [e_emb, at_emb, a] @ W1 + b1
// grid (64,13), 128 threads
// ============================================================================
__global__ void __launch_bounds__(128) prep_AL(
    const int* __restrict__ e_data, const int* __restrict__ a_data,
    const int* __restrict__ at_data,
    const float* __restrict__ E_e, const float* __restrict__ E_at,
    const float* __restrict__ W1, const float* __restrict__ b1)
{
    int b = blockIdx.x, s0 = blockIdx.y*8, f = threadIdx.x;
    __shared__ float se[8][128], sa[8][128], av[8];
    int cnt = min(8, NS - s0);
    for (int t = 0; t < 8; t++) {
        if (t < cnt) {
            int s = s0 + t;
            int e  = e_data [b*NS + s];
            int at = at_data[b*NS + s];
            se[t][f] = E_e [e *128 + f];
            sa[t][f] = E_at[at*128 + f];
            if (f == 0) av[t] = (float)a_data[b*NS + s];
        } else { se[t][f] = 0.f; sa[t][f] = 0.f; if (f == 0) av[t] = 0.f; }
    }
    __syncthreads();
    float w1sf = g_w1s[f], b1f = b1[f];
    float acc[8];
#pragma unroll
    for (int t = 0; t < 8; t++) acc[t] = b1f + av[t]*w1sf;
    for (int k = 0; k < 128; k++) {
        float w = W1[k*128 + f];
#pragma unroll
        for (int t = 0; t < 8; t++) acc[t] += se[t][k]*w;
    }
    for (int k = 0; k < 128; k++) {
        float w = W1[(128+k)*128 + f];
#pragma unroll
        for (int t = 0; t < 8; t++) acc[t] += sa[t][k]*w;
    }
    for (int t = 0; t < cnt; t++) g_AL[(b*NS + s0 + t)*128 + f] = acc[t];
}

// ============================================================================
// prep_UIT: it_emb @ W4i + b4
// ============================================================================
__global__ void __launch_bounds__(128) prep_UIT(
    const int* __restrict__ it_data, const float* __restrict__ E_it,
    const float* __restrict__ W4, const float* __restrict__ b4)
{
    int b = blockIdx.x, s0 = blockIdx.y*8, f = threadIdx.x;
    __shared__ float si[8][128];
    int cnt = min(8, NS - s0);
    for (int t = 0; t < 8; t++) {
        if (t < cnt) { int it = it_data[b*NS + s0 + t]; si[t][f] = E_it[it*128 + f]; }
        else si[t][f] = 0.f;
    }
    __syncthreads();
    float bf = b4[f];
    float acc[8];
#pragma unroll
    for (int t = 0; t < 8; t++) acc[t] = bf;
    for (int k = 0; k < 128; k++) {
        float wv = W4[(256+k)*128 + f];
#pragma unroll
        for (int t = 0; t < 8; t++) acc[t] += si[t][k]*wv;
    }
    for (int t = 0; t < cnt; t++) g_UIT[(b*NS + s0 + t)*128 + f] = acc[t];
}

// ============================================================================
// prep_G23: feat3 = [AL[t-1], it_emb[t], AL[t]] (384) -> @W2[0:384]+b2 | @W3+b3
// grid (64,10), 256 threads, 10 t per block
// ============================================================================
__global__ void __launch_bounds__(256) prep_G23(
    const int* __restrict__ it_data, const float* __restrict__ E_it,
    const float* __restrict__ W2, const float* __restrict__ b2,
    const float* __restrict__ W3, const float* __restrict__ b3)
{
    int b = blockIdx.x, t0 = blockIdx.y*10;
    int T = min(10, 99 - t0);
    __shared__ float sf[10][384];
    for (int idx = threadIdx.x; idx < T*384; idx += 256) {
        int tt = idx / 384, kk = idx - tt*384;
        int t = t0 + tt;
        float v;
        if (kk < 128)       v = (t == 0) ? 0.f : g_AL[(b*NS + t - 1)*128 + kk];
        else if (kk < 256) { int it = it_data[b*NS + t]; v = E_it[it*128 + (kk-128)]; }
        else                v = g_AL[(b*NS + t)*128 + (kk-256)];
        sf[tt][kk] = v;
    }
    __syncthreads();
    int j = threadIdx.x;
    const float* Wc;
    float bias;
    if (j < 128) { Wc = W2 + j;        bias = b2[j];     }
    else         { Wc = W3 + (j-128);  bias = b3[j-128]; }
    float acc[10];
#pragma unroll
    for (int tt = 0; tt < 10; tt++) acc[tt] = bias;
    for (int k = 0; k < 384; k++) {
        float wv = Wc[k*128];
#pragma unroll
        for (int tt = 0; tt < 10; tt++) acc[tt] += sf[tt][k]*wv;
    }
    for (int tt = 0; tt < T; tt++) g_G23[(b*NS + t0 + tt)*256 + j] = acc[tt];
}

// ============================================================================
// Main persistent scan kernel: one CTA per b, 512 threads (16 warps).
// Rows 0..127 split 8/warp; row 128 handled split-k in phases C/E.
// Column map per lane: {2L, 2L+1, 64+2L, 64+2L+1}  (conflict-free LDS.128/64)
// ============================================================================
__global__ void __launch_bounds__(512, 1) lpkt_main(
    const int* __restrict__ e_data, const float* __restrict__ q_matrix,
    const float* __restrict__ h0, const float* __restrict__ W4)
{
    extern __shared__ float sm[];
    float* sh    = sm;                // 16512 : h[129][128]
    float* sW4h  = sm   + 16512;      // 16384 : k-pair interleaved [k2][c] u64
    float* sW4l  = sW4h + 16384;      // 16384 : [k][f]
    float* sLG   = sW4l + 16384;      // 128
    float* sC    = sLG  + 128;        // 128
    float* sHT   = sC   + 128;        // 128
    float* sQ    = sHT  + 128;        // 2*132
    float* sPart = sQ   + 264;        // 16*128
    float* sG    = sPart+ 2048;       // 256
    float* sCp   = sG   + 256;        // 512
    float* sCp2  = sCp  + 512;        // 512

    const int b = blockIdx.x, tid = threadIdx.x;
    const int w = tid >> 5, lane = tid & 31;

    // ---- init: load weights + h0 + q row 0 ----
    for (int idx = tid; idx < 16384; idx += 512) {
        int k = idx >> 7, c = idx & 127;
        sW4h[(k >> 1)*256 + 2*c + (k & 1)] = W4[idx];        // pair layout
        sW4l[idx] = W4[16384 + idx];
    }
    for (int idx = tid; idx < 16512; idx += 512) sh[idx] = h0[idx];
    {
        int e0 = e_data[b*NS];
        if (tid < NQ) sQ[tid] = q_matrix[(long)e0*NQ + tid];
    }
    __syncthreads();

    // ---- ht0 = (q0 @ h0) / sum(q0) ----
    {
        int f = tid & 127, ch = tid >> 7;
        float acc = 0.f;
        int r0 = ch*33, r1 = min(r0 + 33, 129);
        for (int r = r0; r < r1; r++) acc += sQ[r]*sh[r*128 + f];
        sCp[tid] = acc;
    }
    __syncthreads();
    if (tid < 128) {
        float qs0 = g_QS[b*NS];
        sHT[tid] = __fdividef(sCp[tid] + sCp[128+tid] + sCp[256+tid] + sCp[384+tid], qs0);
    }
    __syncthreads();

    const int rbase = w*8;

    for (int t = 0; t < 99; t++) {
        const float* sQE = sQ + (t & 1)*132;
        float*       sQN = sQ + ((t + 1) & 1)*132;

        // ---- (A) load q_next row; W23T GEMV on h_tilde; UIT prefetch ----
        float ureg = 0.f;
        if (tid < 128) ureg = g_UIT[(b*NS + t)*128 + tid];
        {
            int en = e_data[b*NS + t + 1];
            if (tid < NQ) sQN[tid] = q_matrix[(long)en*NQ + tid];
        }
        {
            float4 hv = ((const float4*)sHT)[lane];
            const float* gbase = g_G23 + (b*NS + t)*256;
#pragma unroll
            for (int i = 0; i < 16; i++) {
                int j = w*16 + i;
                float4 wv = ((const float4*)(g_W23T + j*128))[lane];
                float v = hv.x*wv.x + hv.y*wv.y + hv.z*wv.z + hv.w*wv.w;
                v += __shfl_xor_sync(0xffffffffu, v, 16);
                v += __shfl_xor_sync(0xffffffffu, v, 8);
                v += __shfl_xor_sync(0xffffffffu, v, 4);
                v += __shfl_xor_sync(0xffffffffu, v, 2);
                v += __shfl_xor_sync(0xffffffffu, v, 1);
                if (lane == 0) sG[j] = v + gbase[j];
            }
        }
        __syncthreads();

        // ---- (B) LG = sigmoid(g3) * sigmoid(2*g2)   [(tanh+1)/2 == sigm(2x)]
        if (tid < 128) {
            float g2 = sG[tid], g3 = sG[128 + tid];
            sLG[tid] = sigm(g3) * sigm(2.f*g2);
        }
        __syncthreads();

        // ---- (C) c = LG @ W4l + UIT  (split-k), plus row-128 GEMV split-k ----
        {
            int f = tid & 127, ch = tid >> 7;
            int k0 = ch*32;
            float acc = 0.f, acc128 = 0.f;
            const float* h128 = sh + 128*128;
#pragma unroll 8
            for (int kk = 0; kk < 32; kk++) {
                int k = k0 + kk;
                acc    += sLG[k]*sW4l[k*128 + f];
                acc128 += h128[k]*sW4h[(k >> 1)*256 + 2*f + (k & 1)];
            }
            sCp[tid]  = acc;
            sCp2[tid] = acc128;
        }
        __syncthreads();
        if (tid < 128) sC[tid] = ureg + sCp[tid] + sCp[128+tid] + sCp[256+tid] + sCp[384+tid];
        __syncthreads();

        // ---- (D) rows 0..127: g = h@W4h + c ; h = q_e*LG + sigm(g)*h ----
        {
            float2 la = ((const float2*)sLG)[lane];
            float2 lb = ((const float2*)sLG)[32 + lane];
            float2 ca = ((const float2*)sC)[lane];
            float2 cb = ((const float2*)sC)[32 + lane];

            u64 acc[8][4];
#pragma unroll
            for (int j = 0; j < 8; j++) {
                acc[j][0] = 0ull; acc[j][1] = 0ull; acc[j][2] = 0ull; acc[j][3] = 0ull;
            }
            const ulonglong2* Wq = (const ulonglong2*)sW4h;  // [k2][64] u64-pairs
            const ulonglong2* Hq = (const ulonglong2*)sh;    // [r][32]  u64-pairs

            for (int k4 = 0; k4 < 32; k4++) {
                ulonglong2 wa0 = Wq[(2*k4    )*64 + lane];
                ulonglong2 wb0 = Wq[(2*k4    )*64 + 32 + lane];
                ulonglong2 wa1 = Wq[(2*k4 + 1)*64 + lane];
                ulonglong2 wb1 = Wq[(2*k4 + 1)*64 + 32 + lane];
#pragma unroll
                for (int j = 0; j < 8; j++) {
                    ulonglong2 hq = Hq[(rbase + j)*32 + k4];
                    FMA2(acc[j][0], hq.x, wa0.x);
                    FMA2(acc[j][1], hq.x, wa0.y);
                    FMA2(acc[j][2], hq.x, wb0.x);
                    FMA2(acc[j][3], hq.x, wb0.y);
                    FMA2(acc[j][0], hq.y, wa1.x);
                    FMA2(acc[j][1], hq.y, wa1.y);
                    FMA2(acc[j][2], hq.y, wb1.x);
                    FMA2(acc[j][3], hq.y, wb1.y);
                }
            }

            float2 htpa = make_float2(0.f, 0.f);
            float2 htpb = make_float2(0.f, 0.f);
#pragma unroll
            for (int j = 0; j < 8; j++) {
                int r = rbase + j;
                float2 a0 = unpk(acc[j][0]);
                float2 a1 = unpk(acc[j][1]);
                float2 a2 = unpk(acc[j][2]);
                float2 a3 = unpk(acc[j][3]);
                float g0 = a0.x + a0.y + ca.x;
                float g1 = a1.x + a1.y + ca.y;
                float g2 = a2.x + a2.y + cb.x;
                float g3 = a3.x + a3.y + cb.y;
                float qe = sQE[r], qn = sQN[r];
                float2 hoa = ((const float2*)(sh + r*128))[lane];
                float2 hob = ((const float2*)(sh + r*128))[32 + lane];
                float2 hna, hnb;
                hna.x = qe*la.x + sigm(g0)*hoa.x;
                hna.y = qe*la.y + sigm(g1)*hoa.y;
                hnb.x = qe*lb.x + sigm(g2)*hob.x;
                hnb.y = qe*lb.y + sigm(g3)*hob.y;
                ((float2*)(sh + r*128))[lane]      = hna;
                ((float2*)(sh + r*128))[32 + lane] = hnb;
                htpa.x += qn*hna.x; htpa.y += qn*hna.y;
                htpb.x += qn*hnb.x; htpb.y += qn*hnb.y;
            }
            ((float2*)(sPart + w*128))[lane]      = htpa;
            ((float2*)(sPart + w*128))[32 + lane] = htpb;
        }
        __syncthreads();

        // ---- (E) row 128 update + reduce h_tilde; store; roll ----
        if (tid < 128) {
            float s = 0.f;
#pragma unroll
            for (int ww = 0; ww < 16; ww++) s += sPart[ww*128 + tid];
            float g128 = sCp2[tid] + sCp2[128+tid] + sCp2[256+tid] + sCp2[384+tid] + sC[tid];
            float hold = sh[128*128 + tid];
            float hn = sQE[128]*sLG[tid] + sigm(g128)*hold;
            sh[128*128 + tid] = hn;
            s += sQN[128]*hn;
            float qs = g_QS[b*NS + t + 1];
            float v = __fdividef(s, qs);
            sHT[tid] = v;
            g_HT[(b*NS + t)*128 + tid] = v;
        }
        __syncthreads();
    }
}

// ============================================================================
// Epilogue: pred[b, t+1] = mean_f sigmoid([e_next, h_tilde] @ W5 + b5)
// grid (64,9), 128 threads, 11 t per block
// ============================================================================
__global__ void __launch_bounds__(128) lpkt_epi(
    const int* __restrict__ e_data, const float* __restrict__ E_e,
    const float* __restrict__ b5, float* __restrict__ pred)
{
    int b = blockIdx.x, f = threadIdx.x;
    __shared__ float sx[256];
    __shared__ float sr[4];
    float b5f = b5[f];
    if (blockIdx.y == 0 && f == 0) pred[b*NS] = 0.f;
    for (int tt = 0; tt < 11; tt++) {
        int t = blockIdx.y*11 + tt;          // 9*11 = 99, t in [0,98]
        int en = e_data[b*NS + t + 1];
        __syncthreads();
        sx[f]       = E_e[en*128 + f];
        sx[128 + f] = g_HT[(b*NS + t)*128 + f];
        __syncthreads();
        float acc = b5f;
        const float4* wp = (const float4*)(g_W5T + f*256);
        const float4* xp = (const float4*)sx;
#pragma unroll 8
        for (int k4 = 0; k4 < 64; k4++) {
            float4 wv = wp[k4], xv = xp[k4];
            acc += wv.x*xv.x + wv.y*xv.y + wv.z*xv.z + wv.w*xv.w;
        }
        float v = sigm(acc);
        v += __shfl_xor_sync(0xffffffffu, v, 16);
        v += __shfl_xor_sync(0xffffffffu, v, 8);
        v += __shfl_xor_sync(0xffffffffu, v, 4);
        v += __shfl_xor_sync(0xffffffffu, v, 2);
        v += __shfl_xor_sync(0xffffffffu, v, 1);
        if ((f & 31) == 0) sr[f >> 5] = v;
        __syncthreads();
        if (f == 0) pred[b*NS + t + 1] = (sr[0] + sr[1] + sr[2] + sr[3]) * (1.f/128.f);
    }
}

// ============================================================================
// launch
// ============================================================================
extern "C" void kernel_launch(void* const* d_in, const int* in_sizes, int n_in,
                              void* d_out, int out_size)
{
    const int*   e_data   = (const int*)  d_in[0];
    const int*   a_data   = (const int*)  d_in[1];
    const int*   it_data  = (const int*)  d_in[2];
    const int*   at_data  = (const int*)  d_in[3];
    const float* q_matrix = (const float*)d_in[4];
    const float* h0       = (const float*)d_in[5];
    const float* E_e      = (const float*)d_in[6];
    const float* E_at     = (const float*)d_in[7];
    const float* E_it     = (const float*)d_in[8];
    const float* W1       = (const float*)d_in[9];
    const float* b1       = (const float*)d_in[10];
    const float* W2       = (const float*)d_in[11];
    const float* b2       = (const float*)d_in[12];
    const float* W3       = (const float*)d_in[13];
    const float* b3       = (const float*)d_in[14];
    const float* W4       = (const float*)d_in[15];
    const float* b4       = (const float*)d_in[16];
    const float* W5       = (const float*)d_in[17];
    const float* b5       = (const float*)d_in[18];
    float* pred = (float*)d_out;

    const int SMEM_MAIN = 53256 * 4;   // 213,024 B
    cudaFuncSetAttribute(lpkt_main, cudaFuncAttributeMaxDynamicSharedMemorySize, SMEM_MAIN);

    prep_misc<<<128, 512>>>(W1, W2, W3, W5);
    prep_qs<<<64, 128>>>(e_data, q_matrix);
    prep_AL<<<dim3(64, 13), 128>>>(e_data, a_data, at_data, E_e, E_at, W1, b1);
    prep_UIT<<<dim3(64, 13), 128>>>(it_data, E_it, W4, b4);
    prep_G23<<<dim3(64, 10), 256>>>(it_data, E_it, W2, b2, W3, b3);
    lpkt_main<<<64, 512, SMEM_MAIN>>>(e_data, q_matrix, h0, W4);
    lpkt_epi<<<dim3(64, 9), 128>>>(e_data, E_e, b5, pred);
}

// round 6
// speedup vs baseline: 2.0113x; 1.4153x over previous
#include <cuda_runtime.h>
#include <cuda_bf16.h>

// ---------------------------------------------------------------------------
// LPKT: 99-step recurrence over B=64 independent sequences.
// Prep kernels hoist all non-recurrent linear algebra. Main scan: one 2-CTA
// cluster per batch element (row-split GEMM, SMEM-resident weights, DSMEM
// exchange). Epilogue computes predictions in parallel.
// ---------------------------------------------------------------------------

typedef unsigned long long u64;
typedef unsigned int u32;

#define NB 64
#define NS 100
#define NQ 129   // N_Q + 1
#define DD 128

// -------------------- device scratch (no allocation allowed) ---------------
__device__ __align__(16) float g_AL [NB*NS*DD];    // all_learning
__device__ __align__(16) float g_G23[NB*NS*2*DD];  // feat[0:384]@[W2|W3] + b
__device__ __align__(16) float g_UIT[NB*NS*DD];    // it@W4i + b4
__device__ __align__(16) float g_HT [NB*NS*DD];    // h_tilde per (b,t)
__device__ __align__(16) float g_W23T[2*DD*DD];    // [j][k]: W2r/W3r transposed
__device__ __align__(16) float g_W5T [DD*2*DD];    // [f][k]: W5 transposed
__device__ __align__(16) float g_w1s [DD];         // colsum W1[256:384]
__device__ __align__(16) float g_QS  [NB*NS];      // sum of q row per (b,t)

__device__ __forceinline__ float sigm(float x) {
    return __fdividef(1.f, 1.f + __expf(-x));
}

#define FMA2(d, a, bb) asm("fma.rn.f32x2 %0, %1, %2, %0;" : "+l"(d) : "l"(a), "l"(bb))

__device__ __forceinline__ float2 unpk(u64 v) {
    float2 r;
    asm("mov.b64 {%0, %1}, %2;" : "=f"(r.x), "=f"(r.y) : "l"(v));
    return r;
}

__device__ __forceinline__ u32 smem_u32(const void* p) {
    u32 a;
    asm("{ .reg .u64 t; cvta.to.shared.u64 t, %1; cvt.u32.u64 %0, t; }" : "=r"(a) : "l"(p));
    return a;
}
__device__ __forceinline__ u32 mapa_u32(u32 laddr, u32 r) {
    u32 a;
    asm("mapa.shared::cluster.u32 %0, %1, %2;" : "=r"(a) : "r"(laddr), "r"(r));
    return a;
}
__device__ __forceinline__ void st_cluster_f32(u32 raddr, float v) {
    asm volatile("st.shared::cluster.f32 [%0], %1;" :: "r"(raddr), "f"(v) : "memory");
}
#define CLUSTER_SYNC() do { \
    asm volatile("barrier.cluster.arrive.aligned;" ::: "memory"); \
    asm volatile("barrier.cluster.wait.aligned;"   ::: "memory"); \
} while (0)

// ============================================================================
// prep_misc: W23T (transpose of W2[384:512] | W3[384:512]), W5T, w1sum
// ============================================================================
__global__ void prep_misc(const float* __restrict__ W1, const float* __restrict__ W2,
                          const float* __restrict__ W3, const float* __restrict__ W5)
{
    for (int idx = blockIdx.x*blockDim.x + threadIdx.x; idx < 65536 + 128;
         idx += gridDim.x*blockDim.x) {
        if (idx < 32768) {
            int j = idx >> 7, k = idx & 127;
            g_W23T[idx] = (j < 128) ? W2[(384+k)*128 + j] : W3[(384+k)*128 + (j-128)];
        } else if (idx < 65536) {
            int r = idx - 32768;
            int f = r >> 8, k = r & 255;
            g_W5T[r] = W5[k*128 + f];
        } else {
            int f = idx - 65536;
            float s = 0.f;
            for (int k = 0; k < 128; k++) s += W1[(256+k)*128 + f];
            g_w1s[f] = s;
        }
    }
}

// ============================================================================
// prep_qs: row sums of q_matrix gathered by e_data
// ============================================================================
__global__ void prep_qs(const int* __restrict__ e_data, const float* __restrict__ q_matrix)
{
    int b = blockIdx.x, t = threadIdx.x;
    if (t < NS) {
        int e = e_data[b*NS + t];
        const float* q = q_matrix + (long)e * NQ;
        float s = 0.f;
        for (int i = 0; i < NQ; i++) s += q[i];
        g_QS[b*NS + t] = s;
    }
}

// ============================================================================
// prep_AL: all_learning[b,s,:] = [e_emb, at_emb, a] @ W1 + b1
// ============================================================================
__global__ void __launch_bounds__(128) prep_AL(
    const int* __restrict__ e_data, const int* __restrict__ a_data,
    const int* __restrict__ at_data,
    const float* __restrict__ E_e, const float* __restrict__ E_at,
    const float* __restrict__ W1, const float* __restrict__ b1)
{
    int b = blockIdx.x, s0 = blockIdx.y*8, f = threadIdx.x;
    __shared__ float se[8][128], sa[8][128], av[8];
    int cnt = min(8, NS - s0);
    for (int t = 0; t < 8; t++) {
        if (t < cnt) {
            int s = s0 + t;
            int e  = e_data [b*NS + s];
            int at = at_data[b*NS + s];
            se[t][f] = E_e [e *128 + f];
            sa[t][f] = E_at[at*128 + f];
            if (f == 0) av[t] = (float)a_data[b*NS + s];
        } else { se[t][f] = 0.f; sa[t][f] = 0.f; if (f == 0) av[t] = 0.f; }
    }
    __syncthreads();
    float w1sf = g_w1s[f], b1f = b1[f];
    float acc[8];
#pragma unroll
    for (int t = 0; t < 8; t++) acc[t] = b1f + av[t]*w1sf;
    for (int k = 0; k < 128; k++) {
        float w = W1[k*128 + f];
#pragma unroll
        for (int t = 0; t < 8; t++) acc[t] += se[t][k]*w;
    }
    for (int k = 0; k < 128; k++) {
        float w = W1[(128+k)*128 + f];
#pragma unroll
        for (int t = 0; t < 8; t++) acc[t] += sa[t][k]*w;
    }
    for (int t = 0; t < cnt; t++) g_AL[(b*NS + s0 + t)*128 + f] = acc[t];
}

// ============================================================================
// prep_UIT: it_emb @ W4i + b4
// ============================================================================
__global__ void __launch_bounds__(128) prep_UIT(
    const int* __restrict__ it_data, const float* __restrict__ E_it,
    const float* __restrict__ W4, const float* __restrict__ b4)
{
    int b = blockIdx.x, s0 = blockIdx.y*8, f = threadIdx.x;
    __shared__ float si[8][128];
    int cnt = min(8, NS - s0);
    for (int t = 0; t < 8; t++) {
        if (t < cnt) { int it = it_data[b*NS + s0 + t]; si[t][f] = E_it[it*128 + f]; }
        else si[t][f] = 0.f;
    }
    __syncthreads();
    float bf = b4[f];
    float acc[8];
#pragma unroll
    for (int t = 0; t < 8; t++) acc[t] = bf;
    for (int k = 0; k < 128; k++) {
        float wv = W4[(256+k)*128 + f];
#pragma unroll
        for (int t = 0; t < 8; t++) acc[t] += si[t][k]*wv;
    }
    for (int t = 0; t < cnt; t++) g_UIT[(b*NS + s0 + t)*128 + f] = acc[t];
}

// ============================================================================
// prep_G23: feat3 = [AL[t-1], it_emb[t], AL[t]] (384) -> @W2[0:384]+b2 | @W3+b3
// ============================================================================
__global__ void __launch_bounds__(256) prep_G23(
    const int* __restrict__ it_data, const float* __restrict__ E_it,
    const float* __restrict__ W2, const float* __restrict__ b2,
    const float* __restrict__ W3, const float* __restrict__ b3)
{
    int b = blockIdx.x, t0 = blockIdx.y*10;
    int T = min(10, 99 - t0);
    __shared__ float sf[10][384];
    for (int idx = threadIdx.x; idx < T*384; idx += 256) {
        int tt = idx / 384, kk = idx - tt*384;
        int t = t0 + tt;
        float v;
        if (kk < 128)       v = (t == 0) ? 0.f : g_AL[(b*NS + t - 1)*128 + kk];
        else if (kk < 256) { int it = it_data[b*NS + t]; v = E_it[it*128 + (kk-128)]; }
        else                v = g_AL[(b*NS + t)*128 + (kk-256)];
        sf[tt][kk] = v;
    }
    __syncthreads();
    int j = threadIdx.x;
    const float* Wc;
    float bias;
    if (j < 128) { Wc = W2 + j;        bias = b2[j];     }
    else         { Wc = W3 + (j-128);  bias = b3[j-128]; }
    float acc[10];
#pragma unroll
    for (int tt = 0; tt < 10; tt++) acc[tt] = bias;
    for (int k = 0; k < 384; k++) {
        float wv = Wc[k*128];
#pragma unroll
        for (int tt = 0; tt < 10; tt++) acc[tt] += sf[tt][k]*wv;
    }
    for (int tt = 0; tt < T; tt++) g_G23[(b*NS + t0 + tt)*256 + j] = acc[tt];
}

// ============================================================================
// Main scan: one 2-CTA cluster per b; rank owns 64 h-rows, half of W23T (j),
// half of W4l (k). Row 128 is replicated and updated split-k. 512 threads.
// ============================================================================
#define OFF_SH     0        // 8192 : h rows (local 0..63)
#define OFF_SH128  8192     // 132  : replicated row 128
#define OFF_W4H    8324     // 16384: full W4h, k-pair interleaved
#define OFF_W4L    24708    // 8192 : own k-half of W4l [kk][f]
#define OFF_W23T   32900    // 16384: own j-half of W23T [jj][k]
#define OFF_LG     49284    // 128
#define OFF_C      49412    // 128
#define OFF_HT     49540    // 128
#define OFF_Q      49668    // 264 (2 x 132 double buffer)
#define OFF_G      49932    // 256
#define OFF_PART   50188    // 1024 = [colh][wg 8][64]
#define OFF_CPC    51212    // 512
#define OFF_CPG    51724    // 512
#define OFF_PC     52236    // 128 : peer c partial (written by peer)
#define OFF_PG     52364    // 128 : peer g128 partial
#define OFF_PHT    52492    // 128 : peer h_tilde partial
#define SMEM_FLOATS 52620

__global__ void __launch_bounds__(512, 1) __cluster_dims__(2, 1, 1) lpkt_main(
    const int* __restrict__ e_data, const float* __restrict__ q_matrix,
    const float* __restrict__ h0, const float* __restrict__ W4)
{
    extern __shared__ float sm[];
    float* sh    = sm + OFF_SH;
    float* sh128 = sm + OFF_SH128;
    float* sW4h  = sm + OFF_W4H;
    float* sW4l  = sm + OFF_W4L;
    float* sW23T = sm + OFF_W23T;
    float* sLG   = sm + OFF_LG;
    float* sC    = sm + OFF_C;
    float* sHT   = sm + OFF_HT;
    float* sQ    = sm + OFF_Q;
    float* sG    = sm + OFF_G;
    float* sPart = sm + OFF_PART;
    float* sCpc  = sm + OFF_CPC;
    float* sCpg  = sm + OFF_CPG;
    float* pC    = sm + OFF_PC;
    float* pG    = sm + OFF_PG;
    float* pHT   = sm + OFF_PHT;

    u32 rank;
    asm("mov.u32 %0, %%cluster_ctarank;" : "=r"(rank));
    const u32 peer = rank ^ 1u;
    const int b = blockIdx.x >> 1;
    const int tid = threadIdx.x;
    const int w = tid >> 5, lane = tid & 31;

    const u32 sb = smem_u32(sm);
    const u32 rG   = mapa_u32(sb + OFF_G*4,   peer);
    const u32 rPC  = mapa_u32(sb + OFF_PC*4,  peer);
    const u32 rPG  = mapa_u32(sb + OFF_PG*4,  peer);
    const u32 rPHT = mapa_u32(sb + OFF_PHT*4, peer);

    // ---- init loads ----
    for (int idx = tid; idx < 16384; idx += 512) {
        int k = idx >> 7, c = idx & 127;
        sW4h[(k >> 1)*256 + 2*c + (k & 1)] = W4[idx];      // pair layout
        sW23T[idx] = g_W23T[rank*16384 + idx];             // own j half
    }
    for (int idx = tid; idx < 8192; idx += 512) {
        sW4l[idx] = W4[16384 + (rank*64 + (idx >> 7))*128 + (idx & 127)];
        sh[idx]   = h0[rank*8192 + idx];                   // own 64 rows
    }
    if (tid < 132) sh128[tid] = (tid < 128) ? h0[16384 + tid] : 0.f;
    {
        int e0 = e_data[b*NS];
        if (tid < NQ) sQ[tid] = q_matrix[(long)e0*NQ + tid];
    }
    __syncthreads();
    CLUSTER_SYNC();                                        // peer smem ready

    // ---- ht0 = (q0 @ h0) / sum(q0) (split over ranks) ----
    {
        int f = tid & 127, ch = tid >> 7;
        float acc = 0.f;
        int r0 = ch*16;
#pragma unroll 4
        for (int rr = 0; rr < 16; rr++) {
            int rl = r0 + rr;
            acc += sQ[rank*64 + rl]*sh[rl*128 + f];
        }
        sCpc[tid] = acc;
    }
    __syncthreads();
    float q128_0 = sQ[128];
    float own0 = 0.f;
    if (tid < 128) {
        own0 = sCpc[tid] + sCpc[128+tid] + sCpc[256+tid] + sCpc[384+tid];
        st_cluster_f32(rPHT + tid*4, own0);
    }
    CLUSTER_SYNC();
    if (tid < 128) {
        float qs0 = g_QS[b*NS];
        sHT[tid] = __fdividef(own0 + pHT[tid] + q128_0*sh128[tid], qs0);
    }
    __syncthreads();

    const int rowg = (w & 7)*8;       // local row base (8 rows per warp)
    const int colh = w >> 3;          // column half
    const int c0 = colh*64;

    for (int t = 0; t < 99; t++) {
        const float* sQE = sQ + (t & 1)*132;
        float*       sQN = sQ + ((t + 1) & 1)*132;

        // ---- (1) prefetch UIT; load q_next; GEMV h_tilde @ W23T (own 128 j) ----
        float ureg = 0.f;
        if (tid < 128) ureg = g_UIT[(b*NS + t)*128 + tid];
        {
            int en = e_data[b*NS + t + 1];
            if (tid < NQ) sQN[tid] = q_matrix[(long)en*NQ + tid];
        }
        {
            float4 hv = ((const float4*)sHT)[lane];
            const float* gbase = g_G23 + (b*NS + t)*256 + rank*128;
#pragma unroll
            for (int i = 0; i < 8; i++) {
                int jl = w*8 + i;                      // 0..127 local
                float4 wv = ((const float4*)(sW23T + jl*128))[lane];
                float v = hv.x*wv.x + hv.y*wv.y + hv.z*wv.z + hv.w*wv.w;
                v += __shfl_xor_sync(0xffffffffu, v, 16);
                v += __shfl_xor_sync(0xffffffffu, v, 8);
                v += __shfl_xor_sync(0xffffffffu, v, 4);
                v += __shfl_xor_sync(0xffffffffu, v, 2);
                v += __shfl_xor_sync(0xffffffffu, v, 1);
                if (lane == 0) {
                    int jg = rank*128 + jl;
                    float g = v + gbase[jl];
                    sG[jg] = g;                         // local
                    st_cluster_f32(rG + jg*4, g);       // peer
                }
            }
        }
        CLUSTER_SYNC();                                 // sync1: sG full both

        // ---- (2) LG = sigmoid(g3) * sigmoid(2*g2) ----
        if (tid < 128) {
            float g2 = sG[tid], g3 = sG[128 + tid];
            sLG[tid] = sigm(g3) * sigm(2.f*g2);
        }
        __syncthreads();

        // ---- (3) phase C: partial c = LG@W4l (own k half), partial g128 ----
        {
            int f = tid & 127, ch = tid >> 7;
            float acc = 0.f, acc128 = 0.f;
            int kk0 = ch*16;
#pragma unroll 8
            for (int i = 0; i < 16; i++) {
                int kk = kk0 + i;
                int kg = rank*64 + kk;
                acc    += sLG[kg]*sW4l[kk*128 + f];
                acc128 += sh128[kg]*sW4h[(kg >> 1)*256 + 2*f + (kg & 1)];
            }
            sCpc[tid] = acc;
            sCpg[tid] = acc128;
        }
        __syncthreads();
        float own_c = 0.f, own_g = 0.f;
        if (tid < 128) {
            own_c = sCpc[tid] + sCpc[128+tid] + sCpc[256+tid] + sCpc[384+tid];
            own_g = sCpg[tid] + sCpg[128+tid] + sCpg[256+tid] + sCpg[384+tid];
            st_cluster_f32(rPC + tid*4, own_c);
            st_cluster_f32(rPG + tid*4, own_g);
        }
        CLUSTER_SYNC();                                 // sync2: partials both
        if (tid < 128) {
            float c_tot = own_c + pC[tid] + ureg;
            sC[tid] = c_tot;
            float g128 = own_g + pG[tid] + c_tot;
            float hn = sQE[128]*sLG[tid] + sigm(g128)*sh128[tid];
            sh128[tid] = hn;
        }
        __syncthreads();

        // ---- (4) main GEMM + gated update for own 64 rows (8 rows x 64 cols/warp)
        {
            float2 la = ((const float2*)(sLG + c0))[lane];
            float2 ca = ((const float2*)(sC  + c0))[lane];
            u64 acc[8][2];
#pragma unroll
            for (int j = 0; j < 8; j++) { acc[j][0] = 0ull; acc[j][1] = 0ull; }
            const ulonglong2* Wq = (const ulonglong2*)sW4h;  // [m][64] (m = k>>1)
            const ulonglong2* Hq = (const ulonglong2*)sh;    // [r][32]
            const int wcol = colh*32 + lane;

            for (int k4 = 0; k4 < 32; k4++) {
                ulonglong2 wa = Wq[(2*k4    )*64 + wcol];    // k=4k4,4k4+1
                ulonglong2 wb = Wq[(2*k4 + 1)*64 + wcol];    // k=4k4+2,4k4+3
#pragma unroll
                for (int j = 0; j < 8; j++) {
                    ulonglong2 hq = Hq[(rowg + j)*32 + k4];
                    FMA2(acc[j][0], hq.x, wa.x);
                    FMA2(acc[j][1], hq.x, wa.y);
                    FMA2(acc[j][0], hq.y, wb.x);
                    FMA2(acc[j][1], hq.y, wb.y);
                }
            }

            float2 htp = make_float2(0.f, 0.f);
#pragma unroll
            for (int j = 0; j < 8; j++) {
                int rl = rowg + j;
                int rg = rank*64 + rl;
                float2 a0 = unpk(acc[j][0]);
                float2 a1 = unpk(acc[j][1]);
                float g0 = a0.x + a0.y + ca.x;
                float g1 = a1.x + a1.y + ca.y;
                float qe = sQE[rg], qn = sQN[rg];
                float2 hold = ((const float2*)(sh + rl*128 + c0))[lane];
                float2 hn;
                hn.x = qe*la.x + sigm(g0)*hold.x;
                hn.y = qe*la.y + sigm(g1)*hold.y;
                ((float2*)(sh + rl*128 + c0))[lane] = hn;
                htp.x += qn*hn.x;
                htp.y += qn*hn.y;
            }
            ((float2*)(sPart + colh*512 + (w & 7)*64))[lane] = htp;
        }
        __syncthreads();

        // ---- (5) reduce own h_tilde partial, exchange, combine ----
        float own_p = 0.f;
        if (tid < 128) {
            const float* pp = sPart + (tid >> 6)*512 + (tid & 63);
#pragma unroll
            for (int wg = 0; wg < 8; wg++) own_p += pp[wg*64];
            st_cluster_f32(rPHT + tid*4, own_p);
        }
        CLUSTER_SYNC();                                 // sync3
        if (tid < 128) {
            float qs = g_QS[b*NS + t + 1];
            float v = __fdividef(own_p + pHT[tid] + sQN[128]*sh128[tid], qs);
            sHT[tid] = v;
            if (rank == 0) g_HT[(b*NS + t)*128 + tid] = v;
        }
        __syncthreads();
    }
}

// ============================================================================
// Epilogue: pred[b, t+1] = mean_f sigmoid([e_next, h_tilde] @ W5 + b5)
// ============================================================================
__global__ void __launch_bounds__(128) lpkt_epi(
    const int* __restrict__ e_data, const float* __restrict__ E_e,
    const float* __restrict__ b5, float* __restrict__ pred)
{
    int b = blockIdx.x, f = threadIdx.x;
    __shared__ float sx[256];
    __shared__ float sr[4];
    float b5f = b5[f];
    if (blockIdx.y == 0 && f == 0) pred[b*NS] = 0.f;
    for (int tt = 0; tt < 11; tt++) {
        int t = blockIdx.y*11 + tt;          // 9*11 = 99, t in [0,98]
        int en = e_data[b*NS + t + 1];
        __syncthreads();
        sx[f]       = E_e[en*128 + f];
        sx[128 + f] = g_HT[(b*NS + t)*128 + f];
        __syncthreads();
        float acc = b5f;
        const float4* wp = (const float4*)(g_W5T + f*256);
        const float4* xp = (const float4*)sx;
#pragma unroll 8
        for (int k4 = 0; k4 < 64; k4++) {
            float4 wv = wp[k4], xv = xp[k4];
            acc += wv.x*xv.x + wv.y*xv.y + wv.z*xv.z + wv.w*xv.w;
        }
        float v = sigm(acc);
        v += __shfl_xor_sync(0xffffffffu, v, 16);
        v += __shfl_xor_sync(0xffffffffu, v, 8);
        v += __shfl_xor_sync(0xffffffffu, v, 4);
        v += __shfl_xor_sync(0xffffffffu, v, 2);
        v += __shfl_xor_sync(0xffffffffu, v, 1);
        if ((f & 31) == 0) sr[f >> 5] = v;
        __syncthreads();
        if (f == 0) pred[b*NS + t + 1] = (sr[0] + sr[1] + sr[2] + sr[3]) * (1.f/128.f);
    }
}

// ============================================================================
// launch
// ============================================================================
extern "C" void kernel_launch(void* const* d_in, const int* in_sizes, int n_in,
                              void* d_out, int out_size)
{
    const int*   e_data   = (const int*)  d_in[0];
    const int*   a_data   = (const int*)  d_in[1];
    const int*   it_data  = (const int*)  d_in[2];
    const int*   at_data  = (const int*)  d_in[3];
    const float* q_matrix = (const float*)d_in[4];
    const float* h0       = (const float*)d_in[5];
    const float* E_e      = (const float*)d_in[6];
    const float* E_at     = (const float*)d_in[7];
    const float* E_it     = (const float*)d_in[8];
    const float* W1       = (const float*)d_in[9];
    const float* b1       = (const float*)d_in[10];
    const float* W2       = (const float*)d_in[11];
    const float* b2       = (const float*)d_in[12];
    const float* W3       = (const float*)d_in[13];
    const float* b3       = (const float*)d_in[14];
    const float* W4       = (const float*)d_in[15];
    const float* b4       = (const float*)d_in[16];
    const float* W5       = (const float*)d_in[17];
    const float* b5       = (const float*)d_in[18];
    float* pred = (float*)d_out;

    const int SMEM_MAIN = SMEM_FLOATS * 4;   // 210,480 B
    cudaFuncSetAttribute(lpkt_main, cudaFuncAttributeMaxDynamicSharedMemorySize, SMEM_MAIN);

    prep_misc<<<128, 512>>>(W1, W2, W3, W5);
    prep_qs<<<64, 128>>>(e_data, q_matrix);
    prep_AL<<<dim3(64, 13), 128>>>(e_data, a_data, at_data, E_e, E_at, W1, b1);
    prep_UIT<<<dim3(64, 13), 128>>>(it_data, E_it, W4, b4);
    prep_G23<<<dim3(64, 10), 256>>>(it_data, E_it, W2, b2, W3, b3);
    lpkt_main<<<128, 512, SMEM_MAIN>>>(e_data, q_matrix, h0, W4);
    lpkt_epi<<<dim3(64, 9), 128>>>(e_data, E_e, b5, pred);
}

// round 7
// speedup vs baseline: 2.0158x; 1.0022x over previous
#include <cuda_runtime.h>
#include <cuda_bf16.h>

// ---------------------------------------------------------------------------
// LPKT: 99-step recurrence over B=64 independent sequences.
// Prep kernels hoist all non-recurrent linear algebra. Main scan: one 2-CTA
// cluster per batch element (row-split GEMM, SMEM-resident weights, DSMEM
// exchange). Epilogue computes predictions in parallel.
// ---------------------------------------------------------------------------

typedef unsigned long long u64;
typedef unsigned int u32;

#define NB 64
#define NS 100
#define NQ 129   // N_Q + 1
#define DD 128

// -------------------- device scratch (no allocation allowed) ---------------
__device__ __align__(16) float g_AL [NB*NS*DD];    // all_learning
__device__ __align__(16) float g_G23[NB*NS*2*DD];  // feat[0:384]@[W2|W3] + b
__device__ __align__(16) float g_UIT[NB*NS*DD];    // it@W4i + b4
__device__ __align__(16) float g_HT [NB*NS*DD];    // h_tilde per (b,t)
__device__ __align__(16) float g_W23T[2*DD*DD];    // [j][k]: W2r/W3r transposed
__device__ __align__(16) float g_W5T [DD*2*DD];    // [f][k]: W5 transposed
__device__ __align__(16) float g_w1s [DD];         // colsum W1[256:384]
__device__ __align__(16) float g_QS  [NB*NS];      // sum of q row per (b,t)

__device__ __forceinline__ float sigm(float x) {
    return __fdividef(1.f, 1.f + __expf(-x));
}

#define FMA2(d, a, bb) asm("fma.rn.f32x2 %0, %1, %2, %0;" : "+l"(d) : "l"(a), "l"(bb))

__device__ __forceinline__ float2 unpk(u64 v) {
    float2 r;
    asm("mov.b64 {%0, %1}, %2;" : "=f"(r.x), "=f"(r.y) : "l"(v));
    return r;
}

__device__ __forceinline__ u32 smem_u32(const void* p) {
    u32 a;
    asm("{ .reg .u64 t; cvta.to.shared.u64 t, %1; cvt.u32.u64 %0, t; }" : "=r"(a) : "l"(p));
    return a;
}
__device__ __forceinline__ u32 mapa_u32(u32 laddr, u32 r) {
    u32 a;
    asm("mapa.shared::cluster.u32 %0, %1, %2;" : "=r"(a) : "r"(laddr), "r"(r));
    return a;
}
__device__ __forceinline__ void st_cluster_f32(u32 raddr, float v) {
    asm volatile("st.shared::cluster.f32 [%0], %1;" :: "r"(raddr), "f"(v) : "memory");
}
#define CLUSTER_SYNC() do { \
    asm volatile("barrier.cluster.arrive.aligned;" ::: "memory"); \
    asm volatile("barrier.cluster.wait.aligned;"   ::: "memory"); \
} while (0)

// ============================================================================
// prep_misc: W23T (transpose of W2[384:512] | W3[384:512]), W5T, w1sum
// ============================================================================
__global__ void prep_misc(const float* __restrict__ W1, const float* __restrict__ W2,
                          const float* __restrict__ W3, const float* __restrict__ W5)
{
    for (int idx = blockIdx.x*blockDim.x + threadIdx.x; idx < 65536 + 128;
         idx += gridDim.x*blockDim.x) {
        if (idx < 32768) {
            int j = idx >> 7, k = idx & 127;
            g_W23T[idx] = (j < 128) ? W2[(384+k)*128 + j] : W3[(384+k)*128 + (j-128)];
        } else if (idx < 65536) {
            int r = idx - 32768;
            int f = r >> 8, k = r & 255;
            g_W5T[r] = W5[k*128 + f];
        } else {
            int f = idx - 65536;
            float s = 0.f;
            for (int k = 0; k < 128; k++) s += W1[(256+k)*128 + f];
            g_w1s[f] = s;
        }
    }
}

// ============================================================================
// prep_qs: row sums of q_matrix gathered by e_data
// ============================================================================
__global__ void prep_qs(const int* __restrict__ e_data, const float* __restrict__ q_matrix)
{
    int b = blockIdx.x, t = threadIdx.x;
    if (t < NS) {
        int e = e_data[b*NS + t];
        const float* q = q_matrix + (long)e * NQ;
        float s = 0.f;
        for (int i = 0; i < NQ; i++) s += q[i];
        g_QS[b*NS + t] = s;
    }
}

// ============================================================================
// prep_AL: all_learning[b,s,:] = [e_emb, at_emb, a] @ W1 + b1
// ============================================================================
__global__ void __launch_bounds__(128) prep_AL(
    const int* __restrict__ e_data, const int* __restrict__ a_data,
    const int* __restrict__ at_data,
    const float* __restrict__ E_e, const float* __restrict__ E_at,
    const float* __restrict__ W1, const float* __restrict__ b1)
{
    int b = blockIdx.x, s0 = blockIdx.y*8, f = threadIdx.x;
    __shared__ float se[8][128], sa[8][128], av[8];
    int cnt = min(8, NS - s0);
    for (int t = 0; t < 8; t++) {
        if (t < cnt) {
            int s = s0 + t;
            int e  = e_data [b*NS + s];
            int at = at_data[b*NS + s];
            se[t][f] = E_e [e *128 + f];
            sa[t][f] = E_at[at*128 + f];
            if (f == 0) av[t] = (float)a_data[b*NS + s];
        } else { se[t][f] = 0.f; sa[t][f] = 0.f; if (f == 0) av[t] = 0.f; }
    }
    __syncthreads();
    float w1sf = g_w1s[f], b1f = b1[f];
    float acc[8];
#pragma unroll
    for (int t = 0; t < 8; t++) acc[t] = b1f + av[t]*w1sf;
    for (int k = 0; k < 128; k++) {
        float w = W1[k*128 + f];
#pragma unroll
        for (int t = 0; t < 8; t++) acc[t] += se[t][k]*w;
    }
    for (int k = 0; k < 128; k++) {
        float w = W1[(128+k)*128 + f];
#pragma unroll
        for (int t = 0; t < 8; t++) acc[t] += sa[t][k]*w;
    }
    for (int t = 0; t < cnt; t++) g_AL[(b*NS + s0 + t)*128 + f] = acc[t];
}

// ============================================================================
// prep_UIT: it_emb @ W4i + b4
// ============================================================================
__global__ void __launch_bounds__(128) prep_UIT(
    const int* __restrict__ it_data, const float* __restrict__ E_it,
    const float* __restrict__ W4, const float* __restrict__ b4)
{
    int b = blockIdx.x, s0 = blockIdx.y*8, f = threadIdx.x;
    __shared__ float si[8][128];
    int cnt = min(8, NS - s0);
    for (int t = 0; t < 8; t++) {
        if (t < cnt) { int it = it_data[b*NS + s0 + t]; si[t][f] = E_it[it*128 + f]; }
        else si[t][f] = 0.f;
    }
    __syncthreads();
    float bf = b4[f];
    float acc[8];
#pragma unroll
    for (int t = 0; t < 8; t++) acc[t] = bf;
    for (int k = 0; k < 128; k++) {
        float wv = W4[(256+k)*128 + f];
#pragma unroll
        for (int t = 0; t < 8; t++) acc[t] += si[t][k]*wv;
    }
    for (int t = 0; t < cnt; t++) g_UIT[(b*NS + s0 + t)*128 + f] = acc[t];
}

// ============================================================================
// prep_G23: feat3 = [AL[t-1], it_emb[t], AL[t]] (384) -> @W2[0:384]+b2 | @W3+b3
// ============================================================================
__global__ void __launch_bounds__(256) prep_G23(
    const int* __restrict__ it_data, const float* __restrict__ E_it,
    const float* __restrict__ W2, const float* __restrict__ b2,
    const float* __restrict__ W3, const float* __restrict__ b3)
{
    int b = blockIdx.x, t0 = blockIdx.y*10;
    int T = min(10, 99 - t0);
    __shared__ float sf[10][384];
    for (int idx = threadIdx.x; idx < T*384; idx += 256) {
        int tt = idx / 384, kk = idx - tt*384;
        int t = t0 + tt;
        float v;
        if (kk < 128)       v = (t == 0) ? 0.f : g_AL[(b*NS + t - 1)*128 + kk];
        else if (kk < 256) { int it = it_data[b*NS + t]; v = E_it[it*128 + (kk-128)]; }
        else                v = g_AL[(b*NS + t)*128 + (kk-256)];
        sf[tt][kk] = v;
    }
    __syncthreads();
    int j = threadIdx.x;
    const float* Wc;
    float bias;
    if (j < 128) { Wc = W2 + j;        bias = b2[j];     }
    else         { Wc = W3 + (j-128);  bias = b3[j-128]; }
    float acc[10];
#pragma unroll
    for (int tt = 0; tt < 10; tt++) acc[tt] = bias;
    for (int k = 0; k < 384; k++) {
        float wv = Wc[k*128];
#pragma unroll
        for (int tt = 0; tt < 10; tt++) acc[tt] += sf[tt][k]*wv;
    }
    for (int tt = 0; tt < T; tt++) g_G23[(b*NS + t0 + tt)*256 + j] = acc[tt];
}

// ============================================================================
// Main scan: one 2-CTA cluster per b; rank owns 64 h-rows, half of W23T (j),
// half of W4l (k). Row 128 is replicated and updated split-k. 512 threads.
// ============================================================================
#define OFF_SH     0        // 8192 : h rows (local 0..63)
#define OFF_SH128  8192     // 132  : replicated row 128
#define OFF_W4H    8324     // 16384: full W4h, k-pair interleaved
#define OFF_W4L    24708    // 8192 : own k-half of W4l [kk][f]
#define OFF_W23T   32900    // 16384: own j-half of W23T [jj][k]
#define OFF_LG     49284    // 128
#define OFF_C      49412    // 128
#define OFF_HT     49540    // 128
#define OFF_Q      49668    // 264 (2 x 132 double buffer)
#define OFF_G      49932    // 256
#define OFF_PART   50188    // 1024 = [colh][wg 8][64]
#define OFF_CPC    51212    // 512
#define OFF_CPG    51724    // 512
#define OFF_PC     52236    // 128 : peer c partial (written by peer)
#define OFF_PG     52364    // 128 : peer g128 partial
#define OFF_PHT    52492    // 128 : peer h_tilde partial
#define SMEM_FLOATS 52620

__global__ void __launch_bounds__(512, 1) __cluster_dims__(2, 1, 1) lpkt_main(
    const int* __restrict__ e_data, const float* __restrict__ q_matrix,
    const float* __restrict__ h0, const float* __restrict__ W4)
{
    extern __shared__ float sm[];
    float* sh    = sm + OFF_SH;
    float* sh128 = sm + OFF_SH128;
    float* sW4h  = sm + OFF_W4H;
    float* sW4l  = sm + OFF_W4L;
    float* sW23T = sm + OFF_W23T;
    float* sLG   = sm + OFF_LG;
    float* sC    = sm + OFF_C;
    float* sHT   = sm + OFF_HT;
    float* sQ    = sm + OFF_Q;
    float* sG    = sm + OFF_G;
    float* sPart = sm + OFF_PART;
    float* sCpc  = sm + OFF_CPC;
    float* sCpg  = sm + OFF_CPG;
    float* pC    = sm + OFF_PC;
    float* pG    = sm + OFF_PG;
    float* pHT   = sm + OFF_PHT;

    u32 rank;
    asm("mov.u32 %0, %%cluster_ctarank;" : "=r"(rank));
    const u32 peer = rank ^ 1u;
    const int b = blockIdx.x >> 1;
    const int tid = threadIdx.x;
    const int w = tid >> 5, lane = tid & 31;

    const u32 sb = smem_u32(sm);
    const u32 rG   = mapa_u32(sb + OFF_G*4,   peer);
    const u32 rPC  = mapa_u32(sb + OFF_PC*4,  peer);
    const u32 rPG  = mapa_u32(sb + OFF_PG*4,  peer);
    const u32 rPHT = mapa_u32(sb + OFF_PHT*4, peer);

    // ---- init loads ----
    for (int idx = tid; idx < 16384; idx += 512) {
        int k = idx >> 7, c = idx & 127;
        sW4h[(k >> 1)*256 + 2*c + (k & 1)] = W4[idx];      // pair layout
        sW23T[idx] = g_W23T[rank*16384 + idx];             // own j half
    }
    for (int idx = tid; idx < 8192; idx += 512) {
        sW4l[idx] = W4[16384 + (rank*64 + (idx >> 7))*128 + (idx & 127)];
        sh[idx]   = h0[rank*8192 + idx];                   // own 64 rows
    }
    if (tid < 132) sh128[tid] = (tid < 128) ? h0[16384 + tid] : 0.f;
    {
        int e0 = e_data[b*NS];
        if (tid < NQ) sQ[tid] = q_matrix[(long)e0*NQ + tid];
    }
    __syncthreads();
    CLUSTER_SYNC();                                        // peer smem ready

    // ---- ht0 = (q0 @ h0) / sum(q0) (split over ranks) ----
    {
        int f = tid & 127, ch = tid >> 7;
        float acc = 0.f;
        int r0 = ch*16;
#pragma unroll 4
        for (int rr = 0; rr < 16; rr++) {
            int rl = r0 + rr;
            acc += sQ[rank*64 + rl]*sh[rl*128 + f];
        }
        sCpc[tid] = acc;
    }
    __syncthreads();
    float q128_0 = sQ[128];
    float own0 = 0.f;
    if (tid < 128) {
        own0 = sCpc[tid] + sCpc[128+tid] + sCpc[256+tid] + sCpc[384+tid];
        st_cluster_f32(rPHT + tid*4, own0);
    }
    CLUSTER_SYNC();
    if (tid < 128) {
        float qs0 = g_QS[b*NS];
        sHT[tid] = __fdividef(own0 + pHT[tid] + q128_0*sh128[tid], qs0);
    }
    __syncthreads();

    const int rowg = (w & 7)*8;       // local row base (8 rows per warp)
    const int colh = w >> 3;          // column half
    const int c0 = colh*64;

    for (int t = 0; t < 99; t++) {
        const float* sQE = sQ + (t & 1)*132;
        float*       sQN = sQ + ((t + 1) & 1)*132;

        // ---- (1) prefetch UIT; load q_next; GEMV h_tilde @ W23T (own 128 j) ----
        float ureg = 0.f;
        if (tid < 128) ureg = g_UIT[(b*NS + t)*128 + tid];
        {
            int en = e_data[b*NS + t + 1];
            if (tid < NQ) sQN[tid] = q_matrix[(long)en*NQ + tid];
        }
        {
            float4 hv = ((const float4*)sHT)[lane];
            const float* gbase = g_G23 + (b*NS + t)*256 + rank*128;
#pragma unroll
            for (int i = 0; i < 8; i++) {
                int jl = w*8 + i;                      // 0..127 local
                float4 wv = ((const float4*)(sW23T + jl*128))[lane];
                float v = hv.x*wv.x + hv.y*wv.y + hv.z*wv.z + hv.w*wv.w;
                v += __shfl_xor_sync(0xffffffffu, v, 16);
                v += __shfl_xor_sync(0xffffffffu, v, 8);
                v += __shfl_xor_sync(0xffffffffu, v, 4);
                v += __shfl_xor_sync(0xffffffffu, v, 2);
                v += __shfl_xor_sync(0xffffffffu, v, 1);
                if (lane == 0) {
                    int jg = rank*128 + jl;
                    float g = v + gbase[jl];
                    sG[jg] = g;                         // local
                    st_cluster_f32(rG + jg*4, g);       // peer
                }
            }
        }
        CLUSTER_SYNC();                                 // sync1: sG full both

        // ---- (2) LG = sigmoid(g3) * sigmoid(2*g2) ----
        if (tid < 128) {
            float g2 = sG[tid], g3 = sG[128 + tid];
            sLG[tid] = sigm(g3) * sigm(2.f*g2);
        }
        __syncthreads();

        // ---- (3) phase C: partial c = LG@W4l (own k half), partial g128 ----
        {
            int f = tid & 127, ch = tid >> 7;
            float acc = 0.f, acc128 = 0.f;
            int kk0 = ch*16;
#pragma unroll 8
            for (int i = 0; i < 16; i++) {
                int kk = kk0 + i;
                int kg = rank*64 + kk;
                acc    += sLG[kg]*sW4l[kk*128 + f];
                acc128 += sh128[kg]*sW4h[(kg >> 1)*256 + 2*f + (kg & 1)];
            }
            sCpc[tid] = acc;
            sCpg[tid] = acc128;
        }
        __syncthreads();
        float own_c = 0.f, own_g = 0.f;
        if (tid < 128) {
            own_c = sCpc[tid] + sCpc[128+tid] + sCpc[256+tid] + sCpc[384+tid];
            own_g = sCpg[tid] + sCpg[128+tid] + sCpg[256+tid] + sCpg[384+tid];
            st_cluster_f32(rPC + tid*4, own_c);
            st_cluster_f32(rPG + tid*4, own_g);
        }
        CLUSTER_SYNC();                                 // sync2: partials both
        if (tid < 128) {
            float c_tot = own_c + pC[tid] + ureg;
            sC[tid] = c_tot;
            float g128 = own_g + pG[tid] + c_tot;
            float hn = sQE[128]*sLG[tid] + sigm(g128)*sh128[tid];
            sh128[tid] = hn;
        }
        __syncthreads();

        // ---- (4) main GEMM + gated update for own 64 rows (8 rows x 64 cols/warp)
        {
            float2 la = ((const float2*)(sLG + c0))[lane];
            float2 ca = ((const float2*)(sC  + c0))[lane];
            u64 acc[8][2];
#pragma unroll
            for (int j = 0; j < 8; j++) { acc[j][0] = 0ull; acc[j][1] = 0ull; }
            const ulonglong2* Wq = (const ulonglong2*)sW4h;  // [m][64] (m = k>>1)
            const ulonglong2* Hq = (const ulonglong2*)sh;    // [r][32]
            const int wcol = colh*32 + lane;

            for (int k4 = 0; k4 < 32; k4++) {
                ulonglong2 wa = Wq[(2*k4    )*64 + wcol];    // k=4k4,4k4+1
                ulonglong2 wb = Wq[(2*k4 + 1)*64 + wcol];    // k=4k4+2,4k4+3
#pragma unroll
                for (int j = 0; j < 8; j++) {
                    ulonglong2 hq = Hq[(rowg + j)*32 + k4];
                    FMA2(acc[j][0], hq.x, wa.x);
                    FMA2(acc[j][1], hq.x, wa.y);
                    FMA2(acc[j][0], hq.y, wb.x);
                    FMA2(acc[j][1], hq.y, wb.y);
                }
            }

            float2 htp = make_float2(0.f, 0.f);
#pragma unroll
            for (int j = 0; j < 8; j++) {
                int rl = rowg + j;
                int rg = rank*64 + rl;
                float2 a0 = unpk(acc[j][0]);
                float2 a1 = unpk(acc[j][1]);
                float g0 = a0.x + a0.y + ca.x;
                float g1 = a1.x + a1.y + ca.y;
                float qe = sQE[rg], qn = sQN[rg];
                float2 hold = ((const float2*)(sh + rl*128 + c0))[lane];
                float2 hn;
                hn.x = qe*la.x + sigm(g0)*hold.x;
                hn.y = qe*la.y + sigm(g1)*hold.y;
                ((float2*)(sh + rl*128 + c0))[lane] = hn;
                htp.x += qn*hn.x;
                htp.y += qn*hn.y;
            }
            ((float2*)(sPart + colh*512 + (w & 7)*64))[lane] = htp;
        }
        __syncthreads();

        // ---- (5) reduce own h_tilde partial, exchange, combine ----
        float own_p = 0.f;
        if (tid < 128) {
            const float* pp = sPart + (tid >> 6)*512 + (tid & 63);
#pragma unroll
            for (int wg = 0; wg < 8; wg++) own_p += pp[wg*64];
            st_cluster_f32(rPHT + tid*4, own_p);
        }
        CLUSTER_SYNC();                                 // sync3
        if (tid < 128) {
            float qs = g_QS[b*NS + t + 1];
            float v = __fdividef(own_p + pHT[tid] + sQN[128]*sh128[tid], qs);
            sHT[tid] = v;
            if (rank == 0) g_HT[(b*NS + t)*128 + tid] = v;
        }
        __syncthreads();
    }
}

// ============================================================================
// Epilogue: pred[b, t+1] = mean_f sigmoid([e_next, h_tilde] @ W5 + b5)
// ============================================================================
__global__ void __launch_bounds__(128) lpkt_epi(
    const int* __restrict__ e_data, const float* __restrict__ E_e,
    const float* __restrict__ b5, float* __restrict__ pred)
{
    int b = blockIdx.x, f = threadIdx.x;
    __shared__ float sx[256];
    __shared__ float sr[4];
    float b5f = b5[f];
    if (blockIdx.y == 0 && f == 0) pred[b*NS] = 0.f;
    for (int tt = 0; tt < 11; tt++) {
        int t = blockIdx.y*11 + tt;          // 9*11 = 99, t in [0,98]
        int en = e_data[b*NS + t + 1];
        __syncthreads();
        sx[f]       = E_e[en*128 + f];
        sx[128 + f] = g_HT[(b*NS + t)*128 + f];
        __syncthreads();
        float acc = b5f;
        const float4* wp = (const float4*)(g_W5T + f*256);
        const float4* xp = (const float4*)sx;
#pragma unroll 8
        for (int k4 = 0; k4 < 64; k4++) {
            float4 wv = wp[k4], xv = xp[k4];
            acc += wv.x*xv.x + wv.y*xv.y + wv.z*xv.z + wv.w*xv.w;
        }
        float v = sigm(acc);
        v += __shfl_xor_sync(0xffffffffu, v, 16);
        v += __shfl_xor_sync(0xffffffffu, v, 8);
        v += __shfl_xor_sync(0xffffffffu, v, 4);
        v += __shfl_xor_sync(0xffffffffu, v, 2);
        v += __shfl_xor_sync(0xffffffffu, v, 1);
        if ((f & 31) == 0) sr[f >> 5] = v;
        __syncthreads();
        if (f == 0) pred[b*NS + t + 1] = (sr[0] + sr[1] + sr[2] + sr[3]) * (1.f/128.f);
    }
}

// ============================================================================
// launch
// ============================================================================
extern "C" void kernel_launch(void* const* d_in, const int* in_sizes, int n_in,
                              void* d_out, int out_size)
{
    const int*   e_data   = (const int*)  d_in[0];
    const int*   a_data   = (const int*)  d_in[1];
    const int*   it_data  = (const int*)  d_in[2];
    const int*   at_data  = (const int*)  d_in[3];
    const float* q_matrix = (const float*)d_in[4];
    const float* h0       = (const float*)d_in[5];
    const float* E_e      = (const float*)d_in[6];
    const float* E_at     = (const float*)d_in[7];
    const float* E_it     = (const float*)d_in[8];
    const float* W1       = (const float*)d_in[9];
    const float* b1       = (const float*)d_in[10];
    const float* W2       = (const float*)d_in[11];
    const float* b2       = (const float*)d_in[12];
    const float* W3       = (const float*)d_in[13];
    const float* b3       = (const float*)d_in[14];
    const float* W4       = (const float*)d_in[15];
    const float* b4       = (const float*)d_in[16];
    const float* W5       = (const float*)d_in[17];
    const float* b5       = (const float*)d_in[18];
    float* pred = (float*)d_out;

    const int SMEM_MAIN = SMEM_FLOATS * 4;   // 210,480 B
    cudaFuncSetAttribute(lpkt_main, cudaFuncAttributeMaxDynamicSharedMemorySize, SMEM_MAIN);

    prep_misc<<<128, 512>>>(W1, W2, W3, W5);
    prep_qs<<<64, 128>>>(e_data, q_matrix);
    prep_AL<<<dim3(64, 13), 128>>>(e_data, a_data, at_data, E_e, E_at, W1, b1);
    prep_UIT<<<dim3(64, 13), 128>>>(it_data, E_it, W4, b4);
    prep_G23<<<dim3(64, 10), 256>>>(it_data, E_it, W2, b2, W3, b3);
    lpkt_main<<<128, 512, SMEM_MAIN>>>(e_data, q_matrix, h0, W4);
    lpkt_epi<<<dim3(64, 9), 128>>>(e_data, E_e, b5, pred);
}

// round 9
// speedup vs baseline: 2.1466x; 1.0649x over previous
#include <cuda_runtime.h>
#include <cuda_bf16.h>

typedef unsigned long long u64;
typedef unsigned int u32;

#define NB 64
#define NS 100
#define NQ 129
#define DD 128

// -------------------- device scratch ---------------------------------------
__device__ __align__(16) float g_AL [NB*NS*DD];
__device__ __align__(16) float g_G23[NB*NS*2*DD];
__device__ __align__(16) float g_UIT[NB*NS*DD];
__device__ __align__(16) float g_HT [NB*NS*DD];
__device__ __align__(16) float g_W23T[2*DD*DD];   // [j][k]
__device__ __align__(16) float g_W5T [DD*2*DD];   // [f][k]
__device__ __align__(16) float g_w1s [DD];
__device__ __align__(16) float g_QS  [NB*NS];

__device__ __forceinline__ float sigm(float x) {
    return __fdividef(1.f, 1.f + __expf(-x));
}
#define FMA2(d, a, bb) asm("fma.rn.f32x2 %0, %1, %2, %0;" : "+l"(d) : "l"(a), "l"(bb))
__device__ __forceinline__ float2 unpk(u64 v) {
    float2 r;
    asm("mov.b64 {%0, %1}, %2;" : "=f"(r.x), "=f"(r.y) : "l"(v));
    return r;
}
__device__ __forceinline__ u32 smem_u32(const void* p) {
    u32 a;
    asm("{ .reg .u64 t; cvta.to.shared.u64 t, %1; cvt.u32.u64 %0, t; }" : "=r"(a) : "l"(p));
    return a;
}
__device__ __forceinline__ u32 mapa_u32(u32 laddr, u32 r) {
    u32 a;
    asm("mapa.shared::cluster.u32 %0, %1, %2;" : "=r"(a) : "r"(laddr), "r"(r));
    return a;
}
__device__ __forceinline__ void st_cluster_f32(u32 raddr, float v) {
    asm volatile("st.shared::cluster.f32 [%0], %1;" :: "r"(raddr), "f"(v) : "memory");
}
#define CLUSTER_SYNC() do { \
    asm volatile("barrier.cluster.arrive.aligned;" ::: "memory"); \
    asm volatile("barrier.cluster.wait.aligned;"   ::: "memory"); \
} while (0)
#define MBARRIER_INIT(mb, c) \
    asm volatile("mbarrier.init.shared.b64 [%0], %1;" :: "r"((u32)(mb)), "r"((u32)(c)) : "memory")
#define MBAR_ARRIVE_REMOTE(raddr) \
    asm volatile("mbarrier.arrive.release.cluster.shared::cluster.b64 _, [%0];" :: "r"((u32)(raddr)) : "memory")
#define MBAR_WAIT_CL(mb, par) do { \
    u32 _m = (u32)(mb), _p = (u32)(par), _d; \
    asm volatile("{ .reg .pred p; mbarrier.try_wait.parity.acquire.cluster.shared::cta.b64 p, [%1], %2; selp.b32 %0, 1, 0, p; }" \
                 : "=r"(_d) : "r"(_m), "r"(_p) : "memory"); \
    if (!_d) { \
        asm volatile("{ .reg .pred P1; WL_%=: mbarrier.try_wait.parity.acquire.cluster.shared::cta.b64 P1, [%0], %1, 0x989680; @P1 bra.uni WD_%=; bra.uni WL_%=; WD_%=: }" \
                     :: "r"(_m), "r"(_p) : "memory"); \
    } \
} while (0)
#define FENCE_CLUSTER() asm volatile("fence.acq_rel.cluster;" ::: "memory")
#define BAR_CHAIN()  asm volatile("bar.sync 1, 256;" ::: "memory")
#define BAR_BLOCK()  asm volatile("bar.sync 2, 512;" ::: "memory")

// ============================ prep kernels ==================================
__global__ void prep_misc(const float* __restrict__ W1, const float* __restrict__ W2,
                          const float* __restrict__ W3, const float* __restrict__ W5)
{
    for (int idx = blockIdx.x*blockDim.x + threadIdx.x; idx < 65664;
         idx += gridDim.x*blockDim.x) {
        if (idx < 32768) {
            int j = idx >> 7, k = idx & 127;
            g_W23T[idx] = (j < 128) ? W2[(384+k)*128 + j] : W3[(384+k)*128 + (j-128)];
        } else if (idx < 65536) {
            int r = idx - 32768;
            int f = r >> 8, k = r & 255;
            g_W5T[r] = W5[k*128 + f];
        } else {
            int f = idx - 65536;
            float s = 0.f;
            for (int k = 0; k < 128; k++) s += W1[(256+k)*128 + f];
            g_w1s[f] = s;
        }
    }
}

__global__ void prep_qs(const int* __restrict__ e_data, const float* __restrict__ q_matrix)
{
    int b = blockIdx.x, t = threadIdx.x;
    if (t < NS) {
        int e = e_data[b*NS + t];
        const float* q = q_matrix + (long)e * NQ;
        float s = 0.f;
        for (int i = 0; i < NQ; i++) s += q[i];
        g_QS[b*NS + t] = s;
    }
}

__global__ void __launch_bounds__(128) prep_AL(
    const int* __restrict__ e_data, const int* __restrict__ a_data,
    const int* __restrict__ at_data,
    const float* __restrict__ E_e, const float* __restrict__ E_at,
    const float* __restrict__ W1, const float* __restrict__ b1)
{
    int b = blockIdx.x, s0 = blockIdx.y*8, f = threadIdx.x;
    __shared__ float se[8][128], sa[8][128], av[8];
    int cnt = min(8, NS - s0);
    for (int t = 0; t < 8; t++) {
        if (t < cnt) {
            int s = s0 + t;
            int e  = e_data [b*NS + s];
            int at = at_data[b*NS + s];
            se[t][f] = E_e [e *128 + f];
            sa[t][f] = E_at[at*128 + f];
            if (f == 0) av[t] = (float)a_data[b*NS + s];
        } else { se[t][f] = 0.f; sa[t][f] = 0.f; if (f == 0) av[t] = 0.f; }
    }
    __syncthreads();
    float w1sf = g_w1s[f], b1f = b1[f];
    float acc[8];
#pragma unroll
    for (int t = 0; t < 8; t++) acc[t] = b1f + av[t]*w1sf;
    for (int k = 0; k < 128; k++) {
        float w = W1[k*128 + f];
#pragma unroll
        for (int t = 0; t < 8; t++) acc[t] += se[t][k]*w;
    }
    for (int k = 0; k < 128; k++) {
        float w = W1[(128+k)*128 + f];
#pragma unroll
        for (int t = 0; t < 8; t++) acc[t] += sa[t][k]*w;
    }
    for (int t = 0; t < cnt; t++) g_AL[(b*NS + s0 + t)*128 + f] = acc[t];
}

__global__ void __launch_bounds__(128) prep_UIT(
    const int* __restrict__ it_data, const float* __restrict__ E_it,
    const float* __restrict__ W4, const float* __restrict__ b4)
{
    int b = blockIdx.x, s0 = blockIdx.y*8, f = threadIdx.x;
    __shared__ float si[8][128];
    int cnt = min(8, NS - s0);
    for (int t = 0; t < 8; t++) {
        if (t < cnt) { int it = it_data[b*NS + s0 + t]; si[t][f] = E_it[it*128 + f]; }
        else si[t][f] = 0.f;
    }
    __syncthreads();
    float bf = b4[f];
    float acc[8];
#pragma unroll
    for (int t = 0; t < 8; t++) acc[t] = bf;
    for (int k = 0; k < 128; k++) {
        float wv = W4[(256+k)*128 + f];
#pragma unroll
        for (int t = 0; t < 8; t++) acc[t] += si[t][k]*wv;
    }
    for (int t = 0; t < cnt; t++) g_UIT[(b*NS + s0 + t)*128 + f] = acc[t];
}

__global__ void __launch_bounds__(256) prep_G23(
    const int* __restrict__ it_data, const float* __restrict__ E_it,
    const float* __restrict__ W2, const float* __restrict__ b2,
    const float* __restrict__ W3, const float* __restrict__ b3)
{
    int b = blockIdx.x, t0 = blockIdx.y*10;
    int T = min(10, 99 - t0);
    __shared__ float sf[10][384];
    for (int idx = threadIdx.x; idx < T*384; idx += 256) {
        int tt = idx / 384, kk = idx - tt*384;
        int t = t0 + tt;
        float v;
        if (kk < 128)       v = (t == 0) ? 0.f : g_AL[(b*NS + t - 1)*128 + kk];
        else if (kk < 256) { int it = it_data[b*NS + t]; v = E_it[it*128 + (kk-128)]; }
        else                v = g_AL[(b*NS + t)*128 + (kk-256)];
        sf[tt][kk] = v;
    }
    __syncthreads();
    int j = threadIdx.x;
    const float* Wc;
    float bias;
    if (j < 128) { Wc = W2 + j;        bias = b2[j];     }
    else         { Wc = W3 + (j-128);  bias = b3[j-128]; }
    float acc[10];
#pragma unroll
    for (int tt = 0; tt < 10; tt++) acc[tt] = bias;
    for (int k = 0; k < 384; k++) {
        float wv = Wc[k*128];
#pragma unroll
        for (int tt = 0; tt < 10; tt++) acc[tt] += sf[tt][k]*wv;
    }
    for (int tt = 0; tt < T; tt++) g_G23[(b*NS + t0 + tt)*256 + j] = acc[tt];
}

// ============================ main scan =====================================
// 2-CTA cluster per b. Warps 0..7: GEMM over own 64 rows (8 rows x 128 cols
// each). Warps 8..15: gate chain + row-128 + h_tilde. SMEM float offsets:
#define OFF_SH     0        // 64*128 = 8192
#define OFF_SH128  8192     // 128
#define OFF_W4H    8320     // 16384 (k-pair interleaved)
#define OFF_W4L    24704    // 16384 full [k][f]
#define OFF_LG     41088    // 128
#define OFF_C      41216    // 128
#define OFF_HT     41344    // 128
#define OFF_Q      41472    // 2 x 132 = 264
#define OFF_G      41736    // 256
#define OFF_PART   41992    // 8 x 128 = 1024
#define OFF_CP     43016    // 256
#define OFF_GP     43272    // 256
#define OFF_PHT    43528    // 128 (peer-written h_tilde partial)
#define OFF_MBAR   43656    // 2 u64 mbarriers (16 B)
#define SMEM_FLOATS 43660   // 174,640 B

__global__ void __launch_bounds__(512, 1) __cluster_dims__(2, 1, 1) lpkt_main(
    const int* __restrict__ e_data, const float* __restrict__ q_matrix,
    const float* __restrict__ h0, const float* __restrict__ W4)
{
    extern __shared__ float sm[];
    float* sh    = sm + OFF_SH;
    float* sh128 = sm + OFF_SH128;
    float* sW4h  = sm + OFF_W4H;
    float* sW4l  = sm + OFF_W4L;
    float* sLG   = sm + OFF_LG;
    float* sC    = sm + OFF_C;
    float* sHT   = sm + OFF_HT;
    float* sQ    = sm + OFF_Q;
    float* sG    = sm + OFF_G;
    float* sPart = sm + OFF_PART;
    float* sCp   = sm + OFF_CP;
    float* sGp   = sm + OFF_GP;
    float* pHT   = sm + OFF_PHT;

    u32 rank;
    asm("mov.u32 %0, %%cluster_ctarank;" : "=r"(rank));
    const u32 peer = rank ^ 1u;
    const int b = blockIdx.x >> 1;
    const int tid = threadIdx.x;
    const int w = tid >> 5, lane = tid & 31;

    const u32 sb   = smem_u32(sm);
    const u32 mbG  = sb + OFF_MBAR*4;
    const u32 mbT  = mbG + 8;
    const u32 rmbG = mapa_u32(mbG, peer);
    const u32 rmbT = mapa_u32(mbT, peer);
    const u32 rG   = mapa_u32(sb + OFF_G*4,   peer);
    const u32 rPHT = mapa_u32(sb + OFF_PHT*4, peer);

    // ---- init ----
    for (int idx = tid; idx < 16384; idx += 512) {
        int k = idx >> 7, c = idx & 127;
        sW4h[(k >> 1)*256 + 2*c + (k & 1)] = W4[idx];   // k-pair interleave
        sW4l[idx] = W4[16384 + idx];
    }
    for (int idx = tid; idx < 8192; idx += 512) sh[idx] = h0[rank*8192 + idx];
    if (tid < 128) sh128[tid] = h0[16384 + tid];
    if (tid < NQ) sQ[tid] = q_matrix[(long)e_data[b*NS]*NQ + tid];
    if (tid == 0) { MBARRIER_INIT(mbG, 1); MBARRIER_INIT(mbT, 1); }
    __syncthreads();
    CLUSTER_SYNC();

    // ---- ht0 ----
    {
        int f = tid & 127, qtr = tid >> 7;
        float acc = 0.f;
        for (int rr = 0; rr < 16; rr++) {
            int rl = qtr*16 + rr;
            acc += sQ[rank*64 + rl]*sh[rl*128 + f];
        }
        sPart[tid] = acc;
    }
    __syncthreads();
    float own0 = 0.f;
    if (tid < 128) {
        own0 = sPart[tid] + sPart[128+tid] + sPart[256+tid] + sPart[384+tid];
        st_cluster_f32(rPHT + tid*4, own0);
    }
    CLUSTER_SYNC();
    if (tid < 128)
        sHT[tid] = __fdividef(own0 + pHT[tid] + sQ[128]*sh128[tid], g_QS[b*NS]);
    __syncthreads();

    const int rbase = (w & 7)*8;

    for (int t = 0; t < 99; t++) {
        const float* sQE = sQ + (t & 1)*132;
        float*       sQN = sQ + ((t + 1) & 1)*132;

        if (w < 8) {
            // ================= GEMM warps =================
            u64 acc[8][4];
#pragma unroll
            for (int j = 0; j < 8; j++) {
                acc[j][0] = 0ull; acc[j][1] = 0ull; acc[j][2] = 0ull; acc[j][3] = 0ull;
            }
            const ulonglong2* Wq = (const ulonglong2*)sW4h;
            const ulonglong2* Hq = (const ulonglong2*)sh;
#pragma unroll 2
            for (int k4 = 0; k4 < 32; k4++) {
                ulonglong2 wA0 = Wq[(2*k4    )*64 + lane];
                ulonglong2 wB0 = Wq[(2*k4    )*64 + 32 + lane];
                ulonglong2 wA1 = Wq[(2*k4 + 1)*64 + lane];
                ulonglong2 wB1 = Wq[(2*k4 + 1)*64 + 32 + lane];
#pragma unroll
                for (int j = 0; j < 8; j++) {
                    ulonglong2 hq = Hq[(rbase + j)*32 + k4];
                    FMA2(acc[j][0], hq.x, wA0.x);
                    FMA2(acc[j][1], hq.x, wA0.y);
                    FMA2(acc[j][2], hq.x, wB0.x);
                    FMA2(acc[j][3], hq.x, wB0.y);
                    FMA2(acc[j][0], hq.y, wA1.x);
                    FMA2(acc[j][1], hq.y, wA1.y);
                    FMA2(acc[j][2], hq.y, wB1.x);
                    FMA2(acc[j][3], hq.y, wB1.y);
                }
            }
            BAR_BLOCK();                       // (b): chain results ready

            // epilogue: gate + update own rows, h_tilde partials
            float2 lg0 = ((const float2*)sLG)[lane];
            float2 lg1 = ((const float2*)sLG)[32 + lane];
            float2 c0  = ((const float2*)sC)[lane];
            float2 c1  = ((const float2*)sC)[32 + lane];
            float htp0 = 0.f, htp1 = 0.f, htp2 = 0.f, htp3 = 0.f;
#pragma unroll
            for (int j = 0; j < 8; j++) {
                int rl = rbase + j;
                int rg = rank*64 + rl;
                float2 a0 = unpk(acc[j][0]);
                float2 a1 = unpk(acc[j][1]);
                float2 a2 = unpk(acc[j][2]);
                float2 a3 = unpk(acc[j][3]);
                float g0 = a0.x + a0.y + c0.x;
                float g1 = a1.x + a1.y + c0.y;
                float g2 = a2.x + a2.y + c1.x;
                float g3 = a3.x + a3.y + c1.y;
                float qe = sQE[rg], qn = sQN[rg];
                float2 h0v = ((const float2*)(sh + rl*128))[lane];
                float2 h1v = ((const float2*)(sh + rl*128))[32 + lane];
                float2 hn0, hn1;
                hn0.x = qe*lg0.x + sigm(g0)*h0v.x;
                hn0.y = qe*lg0.y + sigm(g1)*h0v.y;
                hn1.x = qe*lg1.x + sigm(g2)*h1v.x;
                hn1.y = qe*lg1.y + sigm(g3)*h1v.y;
                ((float2*)(sh + rl*128))[lane]      = hn0;
                ((float2*)(sh + rl*128))[32 + lane] = hn1;
                htp0 += qn*hn0.x; htp1 += qn*hn0.y;
                htp2 += qn*hn1.x; htp3 += qn*hn1.y;
            }
            ((float2*)(sPart + w*128))[lane]      = make_float2(htp0, htp1);
            ((float2*)(sPart + w*128))[32 + lane] = make_float2(htp2, htp3);
            BAR_BLOCK();                       // (c): h updated
        } else {
            // ================= chain warps =================
            const int ct = tid - 256;
            float ureg = 0.f;
            if (ct < 128) ureg = g_UIT[(b*NS + t)*128 + ct];
            if (ct < NQ) sQN[ct] = q_matrix[(long)e_data[b*NS + t + 1]*NQ + ct];

            // G = hT @ W23T (own j-half, streamed from L2) + g23; send to peer
            {
                float4 hv = ((const float4*)sHT)[lane];
                const float* gbase = g_G23 + (b*NS + t)*256;
                int cw = ct >> 5;
#pragma unroll 4
                for (int i = 0; i < 16; i++) {
                    int jg = rank*128 + cw*16 + i;
                    float4 wv = ((const float4*)(g_W23T + jg*128))[lane];
                    float v = hv.x*wv.x + hv.y*wv.y + hv.z*wv.z + hv.w*wv.w;
                    v += __shfl_xor_sync(0xffffffffu, v, 16);
                    v += __shfl_xor_sync(0xffffffffu, v, 8);
                    v += __shfl_xor_sync(0xffffffffu, v, 4);
                    v += __shfl_xor_sync(0xffffffffu, v, 2);
                    v += __shfl_xor_sync(0xffffffffu, v, 1);
                    if (lane == 0) {
                        float g = v + gbase[jg];
                        sG[jg] = g;
                        st_cluster_f32(rG + jg*4, g);
                    }
                }
            }
            BAR_CHAIN();
            if (ct == 0) { FENCE_CLUSTER(); MBAR_ARRIVE_REMOTE(rmbG); }
            MBAR_WAIT_CL(mbG, t & 1);
            if (ct < 128) {
                float g2 = sG[ct], g3 = sG[128 + ct];
                sLG[ct] = sigm(g3) * sigm(2.f*g2);
            }
            BAR_CHAIN();

            // c = LG @ W4l (full k, split across 2 halves) ; g128 split-k
            {
                int f = ct & 127, half = ct >> 7;
                int k0 = half*64;
                float accc = 0.f, accg = 0.f;
#pragma unroll 8
                for (int kk = 0; kk < 64; kk++) {
                    int k = k0 + kk;
                    accc += sLG[k]*sW4l[k*128 + f];
                    accg += sh128[k]*sW4h[(k >> 1)*256 + 2*f + (k & 1)];
                }
                sCp[ct] = accc;
                sGp[ct] = accg;
            }
            BAR_CHAIN();
            float cf = 0.f, g128 = 0.f, hn128 = 0.f;
            if (ct < 128) {
                cf = sCp[ct] + sCp[128 + ct] + ureg;
                sC[ct] = cf;
                g128 = sGp[ct] + sGp[128 + ct];
            }
            BAR_BLOCK();                       // (b)

            if (ct < 128) {
                hn128 = sQE[128]*sLG[ct] + sigm(g128 + cf)*sh128[ct];
                sh128[ct] = hn128;
            }
            BAR_BLOCK();                       // (c)

            // h_tilde: reduce own partials, exchange, combine
            float ownp = 0.f;
            if (ct < 128) {
#pragma unroll
                for (int ww = 0; ww < 8; ww++) ownp += sPart[ww*128 + ct];
                st_cluster_f32(rPHT + ct*4, ownp);
            }
            BAR_CHAIN();
            if (ct == 0) { FENCE_CLUSTER(); MBAR_ARRIVE_REMOTE(rmbT); }
            MBAR_WAIT_CL(mbT, t & 1);
            if (ct < 128) {
                float v = __fdividef(ownp + pHT[ct] + sQN[128]*hn128,
                                     g_QS[b*NS + t + 1]);
                sHT[ct] = v;
                if (rank == 0) g_HT[(b*NS + t)*128 + ct] = v;
            }
            BAR_CHAIN();
        }
    }
}

// ============================ epilogue ======================================
__global__ void __launch_bounds__(128) lpkt_epi(
    const int* __restrict__ e_data, const float* __restrict__ E_e,
    const float* __restrict__ b5, float* __restrict__ pred)
{
    int b = blockIdx.x, f = threadIdx.x;
    __shared__ float sx[256];
    __shared__ float sr[4];
    float b5f = b5[f];
    if (blockIdx.y == 0 && f == 0) pred[b*NS] = 0.f;
    for (int tt = 0; tt < 11; tt++) {
        int t = blockIdx.y*11 + tt;
        int en = e_data[b*NS + t + 1];
        __syncthreads();
        sx[f]       = E_e[en*128 + f];
        sx[128 + f] = g_HT[(b*NS + t)*128 + f];
        __syncthreads();
        float acc = b5f;
        const float4* wp = (const float4*)(g_W5T + f*256);
        const float4* xp = (const float4*)sx;
#pragma unroll 8
        for (int k4 = 0; k4 < 64; k4++) {
            float4 wv = wp[k4], xv = xp[k4];
            acc += wv.x*xv.x + wv.y*xv.y + wv.z*xv.z + wv.w*xv.w;
        }
        float v = sigm(acc);
        v += __shfl_xor_sync(0xffffffffu, v, 16);
        v += __shfl_xor_sync(0xffffffffu, v, 8);
        v += __shfl_xor_sync(0xffffffffu, v, 4);
        v += __shfl_xor_sync(0xffffffffu, v, 2);
        v += __shfl_xor_sync(0xffffffffu, v, 1);
        if ((f & 31) == 0) sr[f >> 5] = v;
        __syncthreads();
        if (f == 0) pred[b*NS + t + 1] = (sr[0] + sr[1] + sr[2] + sr[3]) * (1.f/128.f);
    }
}

// ============================ launch ========================================
extern "C" void kernel_launch(void* const* d_in, const int* in_sizes, int n_in,
                              void* d_out, int out_size)
{
    const int*   e_data   = (const int*)  d_in[0];
    const int*   a_data   = (const int*)  d_in[1];
    const int*   it_data  = (const int*)  d_in[2];
    const int*   at_data  = (const int*)  d_in[3];
    const float* q_matrix = (const float*)d_in[4];
    const float* h0       = (const float*)d_in[5];
    const float* E_e      = (const float*)d_in[6];
    const float* E_at     = (const float*)d_in[7];
    const float* E_it     = (const float*)d_in[8];
    const float* W1       = (const float*)d_in[9];
    const float* b1       = (const float*)d_in[10];
    const float* W2       = (const float*)d_in[11];
    const float* b2       = (const float*)d_in[12];
    const float* W3       = (const float*)d_in[13];
    const float* b3       = (const float*)d_in[14];
    const float* W4       = (const float*)d_in[15];
    const float* b4       = (const float*)d_in[16];
    const float* W5       = (const float*)d_in[17];
    const float* b5       = (const float*)d_in[18];
    float* pred = (float*)d_out;

    const int SMEM_MAIN = SMEM_FLOATS * 4;   // 174,640 B
    cudaFuncSetAttribute(lpkt_main, cudaFuncAttributeMaxDynamicSharedMemorySize, SMEM_MAIN);

    prep_misc<<<128, 512>>>(W1, W2, W3, W5);
    prep_qs<<<64, 128>>>(e_data, q_matrix);
    prep_AL<<<dim3(64, 13), 128>>>(e_data, a_data, at_data, E_e, E_at, W1, b1);
    prep_UIT<<<dim3(64, 13), 128>>>(it_data, E_it, W4, b4);
    prep_G23<<<dim3(64, 10), 256>>>(it_data, E_it, W2, b2, W3, b3);
    lpkt_main<<<128, 512, SMEM_MAIN>>>(e_data, q_matrix, h0, W4);
    lpkt_epi<<<dim3(64, 9), 128>>>(e_data, E_e, b5, pred);
}

// round 10
// speedup vs baseline: 2.2269x; 1.0374x over previous
#include <cuda_runtime.h>
#include <cuda_bf16.h>

typedef unsigned long long u64;
typedef unsigned int u32;

#define NB 64
#define NS 100
#define NQ 129
#define DD 128

// -------------------- device scratch ---------------------------------------
__device__ __align__(16) float g_AL [NB*NS*DD];
__device__ __align__(16) float g_G23[NB*NS*2*DD];
__device__ __align__(16) float g_UIT[NB*NS*DD];
__device__ __align__(16) float g_HT [NB*NS*DD];
__device__ __align__(16) float g_W5T [DD*2*DD];   // [f][k]
__device__ __align__(16) float g_w1s [DD];
__device__ __align__(16) float g_QS  [NB*NS];

__device__ __forceinline__ float sigm(float x) {
    return __fdividef(1.f, 1.f + __expf(-x));
}
#define FMA2(d, a, bb) asm("fma.rn.f32x2 %0, %1, %2, %0;" : "+l"(d) : "l"(a), "l"(bb))
__device__ __forceinline__ float2 unpk(u64 v) {
    float2 r;
    asm("mov.b64 {%0, %1}, %2;" : "=f"(r.x), "=f"(r.y) : "l"(v));
    return r;
}
__device__ __forceinline__ u32 smem_u32(const void* p) {
    u32 a;
    asm("{ .reg .u64 t; cvta.to.shared.u64 t, %1; cvt.u32.u64 %0, t; }" : "=r"(a) : "l"(p));
    return a;
}
__device__ __forceinline__ u32 mapa_u32(u32 laddr, u32 r) {
    u32 a;
    asm("mapa.shared::cluster.u32 %0, %1, %2;" : "=r"(a) : "r"(laddr), "r"(r));
    return a;
}
__device__ __forceinline__ void st_cluster_f32(u32 raddr, float v) {
    asm volatile("st.shared::cluster.f32 [%0], %1;" :: "r"(raddr), "f"(v) : "memory");
}
#define CLUSTER_SYNC() do { \
    asm volatile("barrier.cluster.arrive.aligned;" ::: "memory"); \
    asm volatile("barrier.cluster.wait.aligned;"   ::: "memory"); \
} while (0)
#define MBARRIER_INIT(mb, c) \
    asm volatile("mbarrier.init.shared.b64 [%0], %1;" :: "r"((u32)(mb)), "r"((u32)(c)) : "memory")
#define MBAR_ARRIVE_REMOTE(raddr) \
    asm volatile("mbarrier.arrive.release.cluster.shared::cluster.b64 _, [%0];" :: "r"((u32)(raddr)) : "memory")
#define MBAR_WAIT_CL(mb, par) do { \
    u32 _m = (u32)(mb), _p = (u32)(par), _d; \
    asm volatile("{ .reg .pred p; mbarrier.try_wait.parity.acquire.cluster.shared::cta.b64 p, [%1], %2; selp.b32 %0, 1, 0, p; }" \
                 : "=r"(_d) : "r"(_m), "r"(_p) : "memory"); \
    if (!_d) { \
        asm volatile("{ .reg .pred P1; WL_%=: mbarrier.try_wait.parity.acquire.cluster.shared::cta.b64 P1, [%0], %1, 0x989680; @P1 bra.uni WD_%=; bra.uni WL_%=; WD_%=: }" \
                     :: "r"(_m), "r"(_p) : "memory"); \
    } \
} while (0)
#define FENCE_CLUSTER() asm volatile("fence.acq_rel.cluster;" ::: "memory")
#define BAR_CHAIN()  asm volatile("bar.sync 1, 256;" ::: "memory")
#define BAR_BLOCK()  asm volatile("bar.sync 2, 512;" ::: "memory")

// ============================ prep kernels (3) ==============================
// K0: W5T, w1s, QS
__global__ void prep_base(const float* __restrict__ W1, const float* __restrict__ W5,
                          const int* __restrict__ e_data, const float* __restrict__ q_matrix)
{
    for (int idx = blockIdx.x*blockDim.x + threadIdx.x; idx < 32768 + 128 + NB*NS;
         idx += gridDim.x*blockDim.x) {
        if (idx < 32768) {
            int f = idx >> 8, k = idx & 255;
            g_W5T[idx] = W5[k*128 + f];
        } else if (idx < 32896) {
            int f = idx - 32768;
            float s = 0.f;
            for (int k = 0; k < 128; k++) s += W1[(256+k)*128 + f];
            g_w1s[f] = s;
        } else {
            int r = idx - 32896;
            int e = e_data[r];
            const float* q = q_matrix + (long)e * NQ;
            float s = 0.f;
            for (int i = 0; i < NQ; i++) s += q[i];
            g_QS[r] = s;
        }
    }
}

// K1: AL + UIT fused. grid (64,13), 128 threads.
__global__ void __launch_bounds__(128) prep_ALUIT(
    const int* __restrict__ e_data, const int* __restrict__ a_data,
    const int* __restrict__ at_data, const int* __restrict__ it_data,
    const float* __restrict__ E_e, const float* __restrict__ E_at,
    const float* __restrict__ E_it,
    const float* __restrict__ W1, const float* __restrict__ b1,
    const float* __restrict__ W4, const float* __restrict__ b4)
{
    int b = blockIdx.x, s0 = blockIdx.y*8, f = threadIdx.x;
    __shared__ float se[8][128], sa[8][128], si[8][128], av[8];
    int cnt = min(8, NS - s0);
    for (int t = 0; t < 8; t++) {
        if (t < cnt) {
            int s = s0 + t;
            se[t][f] = E_e [e_data [b*NS + s]*128 + f];
            sa[t][f] = E_at[at_data[b*NS + s]*128 + f];
            si[t][f] = E_it[it_data[b*NS + s]*128 + f];
            if (f == 0) av[t] = (float)a_data[b*NS + s];
        } else { se[t][f] = 0.f; sa[t][f] = 0.f; si[t][f] = 0.f; if (f == 0) av[t] = 0.f; }
    }
    __syncthreads();
    float w1sf = g_w1s[f], b1f = b1[f], b4f = b4[f];
    float acc[8], acu[8];
#pragma unroll
    for (int t = 0; t < 8; t++) { acc[t] = b1f + av[t]*w1sf; acu[t] = b4f; }
    for (int k = 0; k < 128; k++) {
        float w = W1[k*128 + f];
#pragma unroll
        for (int t = 0; t < 8; t++) acc[t] += se[t][k]*w;
    }
    for (int k = 0; k < 128; k++) {
        float w = W1[(128+k)*128 + f];
#pragma unroll
        for (int t = 0; t < 8; t++) acc[t] += sa[t][k]*w;
    }
    for (int k = 0; k < 128; k++) {
        float w = W4[(256+k)*128 + f];
#pragma unroll
        for (int t = 0; t < 8; t++) acu[t] += si[t][k]*w;
    }
    for (int t = 0; t < cnt; t++) {
        g_AL [(b*NS + s0 + t)*128 + f] = acc[t];
        g_UIT[(b*NS + s0 + t)*128 + f] = acu[t];
    }
}

// K2: G23 precompute (needs g_AL)
__global__ void __launch_bounds__(256) prep_G23(
    const int* __restrict__ it_data, const float* __restrict__ E_it,
    const float* __restrict__ W2, const float* __restrict__ b2,
    const float* __restrict__ W3, const float* __restrict__ b3)
{
    int b = blockIdx.x, t0 = blockIdx.y*10;
    int T = min(10, 99 - t0);
    __shared__ float sf[10][384];
    for (int idx = threadIdx.x; idx < T*384; idx += 256) {
        int tt = idx / 384, kk = idx - tt*384;
        int t = t0 + tt;
        float v;
        if (kk < 128)       v = (t == 0) ? 0.f : g_AL[(b*NS + t - 1)*128 + kk];
        else if (kk < 256) { int it = it_data[b*NS + t]; v = E_it[it*128 + (kk-128)]; }
        else                v = g_AL[(b*NS + t)*128 + (kk-256)];
        sf[tt][kk] = v;
    }
    __syncthreads();
    int j = threadIdx.x;
    const float* Wc;
    float bias;
    if (j < 128) { Wc = W2 + j;        bias = b2[j];     }
    else         { Wc = W3 + (j-128);  bias = b3[j-128]; }
    float acc[10];
#pragma unroll
    for (int tt = 0; tt < 10; tt++) acc[tt] = bias;
    for (int k = 0; k < 384; k++) {
        float wv = Wc[k*128];
#pragma unroll
        for (int tt = 0; tt < 10; tt++) acc[tt] += sf[tt][k]*wv;
    }
    for (int tt = 0; tt < T; tt++) g_G23[(b*NS + t0 + tt)*256 + j] = acc[tt];
}

// ============================ main scan =====================================
// 2-CTA cluster per b. Warps 0..7: GEMM (8 rows x 128 cols each).
// Warps 8..15: gate chain (G redundant from L2, LG, c-GEMV, row-128) +
// h_tilde reduce with ONE DSMEM exchange per step.
#define OFF_SH     0        // 8192
#define OFF_SH128  8192     // 128
#define OFF_W4H    8320     // 16384 (k-pair interleaved)
#define OFF_W4L    24704    // 16384 [k][f]
#define OFF_LG     41088    // 128
#define OFF_C      41216    // 128
#define OFF_HT     41344    // 128
#define OFF_Q      41472    // 264
#define OFF_G      41736    // 256
#define OFF_PART   41992    // 1024
#define OFF_CP     43016    // 256
#define OFF_GP     43272    // 256
#define OFF_PHT    43528    // 128
#define OFF_MBAR   43656    // u64 mbar (174624 B, 8-aligned)
#define SMEM_FLOATS 43660   // 174,640 B

__global__ void __launch_bounds__(512, 1) __cluster_dims__(2, 1, 1) lpkt_main(
    const int* __restrict__ e_data, const float* __restrict__ q_matrix,
    const float* __restrict__ h0, const float* __restrict__ W4,
    const float* __restrict__ W2, const float* __restrict__ W3)
{
    extern __shared__ float sm[];
    float* sh    = sm + OFF_SH;
    float* sh128 = sm + OFF_SH128;
    float* sW4h  = sm + OFF_W4H;
    float* sW4l  = sm + OFF_W4L;
    float* sLG   = sm + OFF_LG;
    float* sC    = sm + OFF_C;
    float* sHT   = sm + OFF_HT;
    float* sQ    = sm + OFF_Q;
    float* sG    = sm + OFF_G;
    float* sPart = sm + OFF_PART;
    float* sCp   = sm + OFF_CP;
    float* sGp   = sm + OFF_GP;
    float* pHT   = sm + OFF_PHT;

    u32 rank;
    asm("mov.u32 %0, %%cluster_ctarank;" : "=r"(rank));
    const u32 peer = rank ^ 1u;
    const int b = blockIdx.x >> 1;
    const int tid = threadIdx.x;
    const int w = tid >> 5, lane = tid & 31;

    const u32 sb   = smem_u32(sm);
    const u32 mbT  = sb + OFF_MBAR*4;
    const u32 rmbT = mapa_u32(mbT, peer);
    const u32 rPHT = mapa_u32(sb + OFF_PHT*4, peer);

    // ---- init ----
    for (int idx = tid; idx < 16384; idx += 512) {
        int k = idx >> 7, c = idx & 127;
        sW4h[(k >> 1)*256 + 2*c + (k & 1)] = W4[idx];   // k-pair interleave
        sW4l[idx] = W4[16384 + idx];
    }
    for (int idx = tid; idx < 8192; idx += 512) sh[idx] = h0[rank*8192 + idx];
    if (tid < 128) sh128[tid] = h0[16384 + tid];
    if (tid < NQ) sQ[tid] = q_matrix[(long)e_data[b*NS]*NQ + tid];
    if (tid == 0) MBARRIER_INIT(mbT, 1);
    __syncthreads();
    CLUSTER_SYNC();

    // ---- ht0 ----
    {
        int f = tid & 127, qtr = tid >> 7;
        float acc = 0.f;
        for (int rr = 0; rr < 16; rr++) {
            int rl = qtr*16 + rr;
            acc += sQ[rank*64 + rl]*sh[rl*128 + f];
        }
        sPart[tid] = acc;
    }
    __syncthreads();
    float own0 = 0.f;
    if (tid < 128) {
        own0 = sPart[tid] + sPart[128+tid] + sPart[256+tid] + sPart[384+tid];
        st_cluster_f32(rPHT + tid*4, own0);
    }
    CLUSTER_SYNC();
    if (tid < 128)
        sHT[tid] = __fdividef(own0 + pHT[tid] + sQ[128]*sh128[tid], g_QS[b*NS]);
    __syncthreads();

    const int rbase = (w & 7)*8;

    for (int t = 0; t < 99; t++) {
        const float* sQE = sQ + (t & 1)*132;
        float*       sQN = sQ + ((t + 1) & 1)*132;

        if (w < 8) {
            // ================= GEMM warps =================
            u64 acc[8][4];
#pragma unroll
            for (int j = 0; j < 8; j++) {
                acc[j][0] = 0ull; acc[j][1] = 0ull; acc[j][2] = 0ull; acc[j][3] = 0ull;
            }
            const ulonglong2* Wq = (const ulonglong2*)sW4h;
            const ulonglong2* Hq = (const ulonglong2*)sh;
#pragma unroll 2
            for (int k4 = 0; k4 < 32; k4++) {
                ulonglong2 wA0 = Wq[(2*k4    )*64 + lane];
                ulonglong2 wB0 = Wq[(2*k4    )*64 + 32 + lane];
                ulonglong2 wA1 = Wq[(2*k4 + 1)*64 + lane];
                ulonglong2 wB1 = Wq[(2*k4 + 1)*64 + 32 + lane];
#pragma unroll
                for (int j = 0; j < 8; j++) {
                    ulonglong2 hq = Hq[(rbase + j)*32 + k4];
                    FMA2(acc[j][0], hq.x, wA0.x);
                    FMA2(acc[j][1], hq.x, wA0.y);
                    FMA2(acc[j][2], hq.x, wB0.x);
                    FMA2(acc[j][3], hq.x, wB0.y);
                    FMA2(acc[j][0], hq.y, wA1.x);
                    FMA2(acc[j][1], hq.y, wA1.y);
                    FMA2(acc[j][2], hq.y, wB1.x);
                    FMA2(acc[j][3], hq.y, wB1.y);
                }
            }
            BAR_BLOCK();                       // (b): sLG, sC ready

            float2 lg0 = ((const float2*)sLG)[lane];
            float2 lg1 = ((const float2*)sLG)[32 + lane];
            float2 c0  = ((const float2*)sC)[lane];
            float2 c1  = ((const float2*)sC)[32 + lane];
            float htp0 = 0.f, htp1 = 0.f, htp2 = 0.f, htp3 = 0.f;
#pragma unroll
            for (int j = 0; j < 8; j++) {
                int rl = rbase + j;
                int rg = rank*64 + rl;
                float2 a0 = unpk(acc[j][0]);
                float2 a1 = unpk(acc[j][1]);
                float2 a2 = unpk(acc[j][2]);
                float2 a3 = unpk(acc[j][3]);
                float g0 = a0.x + a0.y + c0.x;
                float g1 = a1.x + a1.y + c0.y;
                float g2 = a2.x + a2.y + c1.x;
                float g3 = a3.x + a3.y + c1.y;
                float qe = sQE[rg], qn = sQN[rg];
                float2 h0v = ((const float2*)(sh + rl*128))[lane];
                float2 h1v = ((const float2*)(sh + rl*128))[32 + lane];
                float2 hn0, hn1;
                hn0.x = qe*lg0.x + sigm(g0)*h0v.x;
                hn0.y = qe*lg0.y + sigm(g1)*h0v.y;
                hn1.x = qe*lg1.x + sigm(g2)*h1v.x;
                hn1.y = qe*lg1.y + sigm(g3)*h1v.y;
                ((float2*)(sh + rl*128))[lane]      = hn0;
                ((float2*)(sh + rl*128))[32 + lane] = hn1;
                htp0 += qn*hn0.x; htp1 += qn*hn0.y;
                htp2 += qn*hn1.x; htp3 += qn*hn1.y;
            }
            ((float2*)(sPart + w*128))[lane]      = make_float2(htp0, htp1);
            ((float2*)(sPart + w*128))[32 + lane] = make_float2(htp2, htp3);
            BAR_BLOCK();                       // (c): h + partials done
        } else {
            // ================= chain warps =================
            const int ct = tid - 256;
            float ureg = 0.f;
            if (ct < 128) ureg = g_UIT[(b*NS + t)*128 + ct];
            if (ct < NQ) sQN[ct] = q_matrix[(long)e_data[b*NS + t + 1]*NQ + ct];

            // G[j] = hT @ W23 (+g23): redundant in both CTAs, coalesced [k][j]
            {
                const float* Wc = (ct < 128) ? (W2 + 49152 + ct)
                                             : (W3 + 49152 + (ct - 128));
                float a0 = 0.f, a1 = 0.f, a2 = 0.f, a3 = 0.f;
#pragma unroll 8
                for (int k = 0; k < 128; k += 4) {
                    a0 += sHT[k    ]*Wc[(k    )*128];
                    a1 += sHT[k + 1]*Wc[(k + 1)*128];
                    a2 += sHT[k + 2]*Wc[(k + 2)*128];
                    a3 += sHT[k + 3]*Wc[(k + 3)*128];
                }
                sG[ct] = (a0 + a1) + (a2 + a3) + g_G23[(b*NS + t)*256 + ct];
            }
            BAR_CHAIN();
            if (ct < 128) {
                float g2 = sG[ct], g3 = sG[128 + ct];
                sLG[ct] = sigm(g3) * sigm(2.f*g2);
            }
            BAR_CHAIN();

            // c = LG @ W4l ; g128 = h128 @ W4h  (k split in halves)
            {
                int f = ct & 127, half = ct >> 7;
                int k0 = half*64;
                float accc = 0.f, accg = 0.f;
#pragma unroll 8
                for (int kk = 0; kk < 64; kk++) {
                    int k = k0 + kk;
                    accc += sLG[k]*sW4l[k*128 + f];
                    accg += sh128[k]*sW4h[(k >> 1)*256 + 2*f + (k & 1)];
                }
                sCp[ct] = accc;
                sGp[ct] = accg;
            }
            BAR_CHAIN();
            float cf = 0.f, hn128 = 0.f;
            if (ct < 128) {
                cf = sCp[ct] + sCp[128 + ct] + ureg;
                sC[ct] = cf;
                float g128 = sGp[ct] + sGp[128 + ct] + cf;
                hn128 = sQE[128]*sLG[ct] + sigm(g128)*sh128[ct];
                sh128[ct] = hn128;
            }
            BAR_BLOCK();                       // (b)
            BAR_BLOCK();                       // (c)

            // h_tilde: reduce own partials, single DSMEM exchange
            float ownp = 0.f;
            if (ct < 128) {
#pragma unroll
                for (int ww = 0; ww < 8; ww++) ownp += sPart[ww*128 + ct];
                st_cluster_f32(rPHT + ct*4, ownp);
            }
            BAR_CHAIN();
            if (ct == 0) { FENCE_CLUSTER(); MBAR_ARRIVE_REMOTE(rmbT); }
            MBAR_WAIT_CL(mbT, t & 1);
            if (ct < 128) {
                float v = __fdividef(ownp + pHT[ct] + sQN[128]*hn128,
                                     g_QS[b*NS + t + 1]);
                sHT[ct] = v;
                if (rank == 0) g_HT[(b*NS + t)*128 + ct] = v;
            }
            BAR_CHAIN();
        }
    }
}

// ============================ epilogue ======================================
__global__ void __launch_bounds__(128) lpkt_epi(
    const int* __restrict__ e_data, const float* __restrict__ E_e,
    const float* __restrict__ b5, float* __restrict__ pred)
{
    int b = blockIdx.x, f = threadIdx.x;
    __shared__ float sx[256];
    __shared__ float sr[4];
    float b5f = b5[f];
    if (blockIdx.y == 0 && f == 0) pred[b*NS] = 0.f;
    for (int tt = 0; tt < 11; tt++) {
        int t = blockIdx.y*11 + tt;
        int en = e_data[b*NS + t + 1];
        __syncthreads();
        sx[f]       = E_e[en*128 + f];
        sx[128 + f] = g_HT[(b*NS + t)*128 + f];
        __syncthreads();
        float acc = b5f;
        const float4* wp = (const float4*)(g_W5T + f*256);
        const float4* xp = (const float4*)sx;
#pragma unroll 8
        for (int k4 = 0; k4 < 64; k4++) {
            float4 wv = wp[k4], xv = xp[k4];
            acc += wv.x*xv.x + wv.y*xv.y + wv.z*xv.z + wv.w*xv.w;
        }
        float v = sigm(acc);
        v += __shfl_xor_sync(0xffffffffu, v, 16);
        v += __shfl_xor_sync(0xffffffffu, v, 8);
        v += __shfl_xor_sync(0xffffffffu, v, 4);
        v += __shfl_xor_sync(0xffffffffu, v, 2);
        v += __shfl_xor_sync(0xffffffffu, v, 1);
        if ((f & 31) == 0) sr[f >> 5] = v;
        __syncthreads();
        if (f == 0) pred[b*NS + t + 1] = (sr[0] + sr[1] + sr[2] + sr[3]) * (1.f/128.f);
    }
}

// ============================ launch ========================================
extern "C" void kernel_launch(void* const* d_in, const int* in_sizes, int n_in,
                              void* d_out, int out_size)
{
    const int*   e_data   = (const int*)  d_in[0];
    const int*   a_data   = (const int*)  d_in[1];
    const int*   it_data  = (const int*)  d_in[2];
    const int*   at_data  = (const int*)  d_in[3];
    const float* q_matrix = (const float*)d_in[4];
    const float* h0       = (const float*)d_in[5];
    const float* E_e      = (const float*)d_in[6];
    const float* E_at     = (const float*)d_in[7];
    const float* E_it     = (const float*)d_in[8];
    const float* W1       = (const float*)d_in[9];
    const float* b1       = (const float*)d_in[10];
    const float* W2       = (const float*)d_in[11];
    const float* b2       = (const float*)d_in[12];
    const float* W3       = (const float*)d_in[13];
    const float* b3       = (const float*)d_in[14];
    const float* W4       = (const float*)d_in[15];
    const float* b4       = (const float*)d_in[16];
    const float* W5       = (const float*)d_in[17];
    const float* b5       = (const float*)d_in[18];
    float* pred = (float*)d_out;

    const int SMEM_MAIN = SMEM_FLOATS * 4;   // 174,640 B
    cudaFuncSetAttribute(lpkt_main, cudaFuncAttributeMaxDynamicSharedMemorySize, SMEM_MAIN);

    prep_base<<<64, 512>>>(W1, W5, e_data, q_matrix);                       // idx 0
    prep_ALUIT<<<dim3(64, 13), 128>>>(e_data, a_data, at_data, it_data,
                                      E_e, E_at, E_it, W1, b1, W4, b4);     // idx 1
    prep_G23<<<dim3(64, 10), 256>>>(it_data, E_it, W2, b2, W3, b3);         // idx 2
    lpkt_main<<<128, 512, SMEM_MAIN>>>(e_data, q_matrix, h0, W4, W2, W3);   // idx 3
    lpkt_epi<<<dim3(64, 9), 128>>>(e_data, E_e, b5, pred);                  // idx 4
}

// round 11
// speedup vs baseline: 2.2954x; 1.0308x over previous
#include <cuda_runtime.h>
#include <cuda_bf16.h>

typedef unsigned long long u64;
typedef unsigned int u32;

#define NB 64
#define NS 100
#define NQ 129
#define DD 128

// -------------------- device scratch ---------------------------------------
__device__ __align__(16) float g_AL [NB*NS*DD];
__device__ __align__(16) float g_G23[NB*NS*2*DD];
__device__ __align__(16) float g_UIT[NB*NS*DD];
__device__ __align__(16) float g_HT [NB*NS*DD];
__device__ __align__(16) float g_W5T [DD*2*DD];   // [f][k]
__device__ __align__(16) float g_w1s [DD];
__device__ __align__(16) float g_QS  [NB*NS];

__device__ __forceinline__ float sigm(float x) {
    return __fdividef(1.f, 1.f + __expf(-x));
}
#define FMA2(d, a, bb) asm("fma.rn.f32x2 %0, %1, %2, %0;" : "+l"(d) : "l"(a), "l"(bb))
__device__ __forceinline__ float2 unpk(u64 v) {
    float2 r;
    asm("mov.b64 {%0, %1}, %2;" : "=f"(r.x), "=f"(r.y) : "l"(v));
    return r;
}
__device__ __forceinline__ u32 smem_u32(const void* p) {
    u32 a;
    asm("{ .reg .u64 t; cvta.to.shared.u64 t, %1; cvt.u32.u64 %0, t; }" : "=r"(a) : "l"(p));
    return a;
}
__device__ __forceinline__ u32 mapa_u32(u32 laddr, u32 r) {
    u32 a;
    asm("mapa.shared::cluster.u32 %0, %1, %2;" : "=r"(a) : "r"(laddr), "r"(r));
    return a;
}
__device__ __forceinline__ void st_cluster_f32(u32 raddr, float v) {
    asm volatile("st.shared::cluster.f32 [%0], %1;" :: "r"(raddr), "f"(v) : "memory");
}
// async-proxy remote store completing the REMOTE CTA's mbarrier (no fence/IVALL)
__device__ __forceinline__ void st_async_f32(u32 raddr, float v, u32 rmbar) {
    asm volatile("st.async.shared::cluster.mbarrier::complete_tx::bytes.f32 [%0], %1, [%2];"
                 :: "r"(raddr), "f"(v), "r"(rmbar) : "memory");
}
#define CLUSTER_SYNC() do { \
    asm volatile("barrier.cluster.arrive.aligned;" ::: "memory"); \
    asm volatile("barrier.cluster.wait.aligned;"   ::: "memory"); \
} while (0)
#define MBARRIER_INIT(mb, c) \
    asm volatile("mbarrier.init.shared.b64 [%0], %1;" :: "r"((u32)(mb)), "r"((u32)(c)) : "memory")
#define MBAR_EXPECT_TX(mb, bytes) \
    asm volatile("mbarrier.arrive.expect_tx.shared.b64 _, [%0], %1;" \
                 :: "r"((u32)(mb)), "r"((u32)(bytes)) : "memory")
#define MBAR_WAIT(mb, par) do { \
    u32 _m = (u32)(mb), _p = (u32)(par), _d; \
    asm volatile("{ .reg .pred p; mbarrier.try_wait.parity.acquire.cta.shared::cta.b64 p, [%1], %2; selp.b32 %0, 1, 0, p; }" \
                 : "=r"(_d) : "r"(_m), "r"(_p) : "memory"); \
    if (!_d) { \
        asm volatile("{ .reg .pred P1; WL_%=: mbarrier.try_wait.parity.acquire.cta.shared::cta.b64 P1, [%0], %1, 0x989680; @P1 bra.uni WD_%=; bra.uni WL_%=; WD_%=: }" \
                     :: "r"(_m), "r"(_p) : "memory"); \
    } \
} while (0)
#define BAR_CHAIN()   asm volatile("bar.sync 1, 256;" ::: "memory")
#define BAR3_SYNC()   asm volatile("bar.sync 3, 512;" ::: "memory")
#define BAR3_ARRIVE() asm volatile("bar.arrive 3, 512;" ::: "memory")
#define BAR4_SYNC()   asm volatile("bar.sync 4, 512;" ::: "memory")
#define BAR4_ARRIVE() asm volatile("bar.arrive 4, 512;" ::: "memory")

// ============================ prep kernels (3) ==============================
__global__ void prep_base(const float* __restrict__ W1, const float* __restrict__ W5,
                          const int* __restrict__ e_data, const float* __restrict__ q_matrix)
{
    for (int idx = blockIdx.x*blockDim.x + threadIdx.x; idx < 32768 + 128 + NB*NS;
         idx += gridDim.x*blockDim.x) {
        if (idx < 32768) {
            int f = idx >> 8, k = idx & 255;
            g_W5T[idx] = W5[k*128 + f];
        } else if (idx < 32896) {
            int f = idx - 32768;
            float s = 0.f;
            for (int k = 0; k < 128; k++) s += W1[(256+k)*128 + f];
            g_w1s[f] = s;
        } else {
            int r = idx - 32896;
            int e = e_data[r];
            const float* q = q_matrix + (long)e * NQ;
            float s = 0.f;
            for (int i = 0; i < NQ; i++) s += q[i];
            g_QS[r] = s;
        }
    }
}

__global__ void __launch_bounds__(128) prep_ALUIT(
    const int* __restrict__ e_data, const int* __restrict__ a_data,
    const int* __restrict__ at_data, const int* __restrict__ it_data,
    const float* __restrict__ E_e, const float* __restrict__ E_at,
    const float* __restrict__ E_it,
    const float* __restrict__ W1, const float* __restrict__ b1,
    const float* __restrict__ W4, const float* __restrict__ b4)
{
    int b = blockIdx.x, s0 = blockIdx.y*8, f = threadIdx.x;
    __shared__ float se[8][128], sa[8][128], si[8][128], av[8];
    int cnt = min(8, NS - s0);
    for (int t = 0; t < 8; t++) {
        if (t < cnt) {
            int s = s0 + t;
            se[t][f] = E_e [e_data [b*NS + s]*128 + f];
            sa[t][f] = E_at[at_data[b*NS + s]*128 + f];
            si[t][f] = E_it[it_data[b*NS + s]*128 + f];
            if (f == 0) av[t] = (float)a_data[b*NS + s];
        } else { se[t][f] = 0.f; sa[t][f] = 0.f; si[t][f] = 0.f; if (f == 0) av[t] = 0.f; }
    }
    __syncthreads();
    float w1sf = g_w1s[f], b1f = b1[f], b4f = b4[f];
    float acc[8], acu[8];
#pragma unroll
    for (int t = 0; t < 8; t++) { acc[t] = b1f + av[t]*w1sf; acu[t] = b4f; }
    for (int k = 0; k < 128; k++) {
        float w = W1[k*128 + f];
#pragma unroll
        for (int t = 0; t < 8; t++) acc[t] += se[t][k]*w;
    }
    for (int k = 0; k < 128; k++) {
        float w = W1[(128+k)*128 + f];
#pragma unroll
        for (int t = 0; t < 8; t++) acc[t] += sa[t][k]*w;
    }
    for (int k = 0; k < 128; k++) {
        float w = W4[(256+k)*128 + f];
#pragma unroll
        for (int t = 0; t < 8; t++) acu[t] += si[t][k]*w;
    }
    for (int t = 0; t < cnt; t++) {
        g_AL [(b*NS + s0 + t)*128 + f] = acc[t];
        g_UIT[(b*NS + s0 + t)*128 + f] = acu[t];
    }
}

__global__ void __launch_bounds__(256) prep_G23(
    const int* __restrict__ it_data, const float* __restrict__ E_it,
    const float* __restrict__ W2, const float* __restrict__ b2,
    const float* __restrict__ W3, const float* __restrict__ b3)
{
    int b = blockIdx.x, t0 = blockIdx.y*10;
    int T = min(10, 99 - t0);
    __shared__ float sf[10][384];
    for (int idx = threadIdx.x; idx < T*384; idx += 256) {
        int tt = idx / 384, kk = idx - tt*384;
        int t = t0 + tt;
        float v;
        if (kk < 128)       v = (t == 0) ? 0.f : g_AL[(b*NS + t - 1)*128 + kk];
        else if (kk < 256) { int it = it_data[b*NS + t]; v = E_it[it*128 + (kk-128)]; }
        else                v = g_AL[(b*NS + t)*128 + (kk-256)];
        sf[tt][kk] = v;
    }
    __syncthreads();
    int j = threadIdx.x;
    const float* Wc;
    float bias;
    if (j < 128) { Wc = W2 + j;        bias = b2[j];     }
    else         { Wc = W3 + (j-128);  bias = b3[j-128]; }
    float acc[10];
#pragma unroll
    for (int tt = 0; tt < 10; tt++) acc[tt] = bias;
    for (int k = 0; k < 384; k++) {
        float wv = Wc[k*128];
#pragma unroll
        for (int tt = 0; tt < 10; tt++) acc[tt] += sf[tt][k]*wv;
    }
    for (int tt = 0; tt < T; tt++) g_G23[(b*NS + t0 + tt)*256 + j] = acc[tt];
}

// ============================ main scan =====================================
// 2-CTA cluster per b. Warps 0..7: GEMM (8 rows x 128 cols) -> decoupled via
// bar.arrive/bar.sync from chain warps 8..15 (gate chain + DSMEM st.async).
#define OFF_SH     0        // 8192
#define OFF_SH128  8192     // 128
#define OFF_W4H    8320     // 16384 (k-pair interleaved)
#define OFF_W4L    24704    // 16384 [k][f]
#define OFF_LG     41088    // 128
#define OFF_C      41216    // 128
#define OFF_HT     41344    // 128
#define OFF_Q      41472    // 264
#define OFF_G      41736    // 256
#define OFF_PART   41992    // 1024
#define OFF_CP     43016    // 256
#define OFF_GP     43272    // 256
#define OFF_PHT    43528    // 128
#define OFF_MBAR   43656    // u64 mbar
#define SMEM_FLOATS 43660   // 174,640 B

__global__ void __launch_bounds__(512, 1) __cluster_dims__(2, 1, 1) lpkt_main(
    const int* __restrict__ e_data, const float* __restrict__ q_matrix,
    const float* __restrict__ h0, const float* __restrict__ W4,
    const float* __restrict__ W2, const float* __restrict__ W3)
{
    extern __shared__ float sm[];
    float* sh    = sm + OFF_SH;
    float* sh128 = sm + OFF_SH128;
    float* sW4h  = sm + OFF_W4H;
    float* sW4l  = sm + OFF_W4L;
    float* sLG   = sm + OFF_LG;
    float* sC    = sm + OFF_C;
    float* sHT   = sm + OFF_HT;
    float* sQ    = sm + OFF_Q;
    float* sG    = sm + OFF_G;
    float* sPart = sm + OFF_PART;
    float* sCp   = sm + OFF_CP;
    float* sGp   = sm + OFF_GP;
    float* pHT   = sm + OFF_PHT;

    u32 rank;
    asm("mov.u32 %0, %%cluster_ctarank;" : "=r"(rank));
    const u32 peer = rank ^ 1u;
    const int b = blockIdx.x >> 1;
    const int tid = threadIdx.x;
    const int w = tid >> 5, lane = tid & 31;

    const u32 sb   = smem_u32(sm);
    const u32 mbT  = sb + OFF_MBAR*4;
    const u32 rmbT = mapa_u32(mbT, peer);
    const u32 rPHT = mapa_u32(sb + OFF_PHT*4, peer);

    // ---- init ----
    for (int idx = tid; idx < 16384; idx += 512) {
        int k = idx >> 7, c = idx & 127;
        sW4h[(k >> 1)*256 + 2*c + (k & 1)] = W4[idx];   // k-pair interleave
        sW4l[idx] = W4[16384 + idx];
    }
    for (int idx = tid; idx < 8192; idx += 512) sh[idx] = h0[rank*8192 + idx];
    if (tid < 128) sh128[tid] = h0[16384 + tid];
    if (tid < NQ) sQ[tid] = q_matrix[(long)e_data[b*NS]*NQ + tid];
    if (tid == 0) MBARRIER_INIT(mbT, 1);
    __syncthreads();
    CLUSTER_SYNC();

    // ---- ht0 (generic-proxy exchange, one-time) ----
    {
        int f = tid & 127, qtr = tid >> 7;
        float acc = 0.f;
        for (int rr = 0; rr < 16; rr++) {
            int rl = qtr*16 + rr;
            acc += sQ[rank*64 + rl]*sh[rl*128 + f];
        }
        sPart[tid] = acc;
    }
    __syncthreads();
    float own0 = 0.f;
    if (tid < 128) {
        own0 = sPart[tid] + sPart[128+tid] + sPart[256+tid] + sPart[384+tid];
        st_cluster_f32(rPHT + tid*4, own0);
    }
    CLUSTER_SYNC();
    if (tid < 128)
        sHT[tid] = __fdividef(own0 + pHT[tid] + sQ[128]*sh128[tid], g_QS[b*NS]);
    __syncthreads();

    const int rbase = (w & 7)*8;

    for (int t = 0; t < 99; t++) {
        const float* sQE = sQ + (t & 1)*132;
        float*       sQN = sQ + ((t + 1) & 1)*132;

        if (w < 8) {
            // ================= GEMM warps =================
            u64 acc[8][4];
#pragma unroll
            for (int j = 0; j < 8; j++) {
                acc[j][0] = 0ull; acc[j][1] = 0ull; acc[j][2] = 0ull; acc[j][3] = 0ull;
            }
            const ulonglong2* Wq = (const ulonglong2*)sW4h;
            const ulonglong2* Hq = (const ulonglong2*)sh;
#pragma unroll 2
            for (int k4 = 0; k4 < 32; k4++) {
                ulonglong2 wA0 = Wq[(2*k4    )*64 + lane];
                ulonglong2 wB0 = Wq[(2*k4    )*64 + 32 + lane];
                ulonglong2 wA1 = Wq[(2*k4 + 1)*64 + lane];
                ulonglong2 wB1 = Wq[(2*k4 + 1)*64 + 32 + lane];
#pragma unroll
                for (int j = 0; j < 8; j++) {
                    ulonglong2 hq = Hq[(rbase + j)*32 + k4];
                    FMA2(acc[j][0], hq.x, wA0.x);
                    FMA2(acc[j][1], hq.x, wA0.y);
                    FMA2(acc[j][2], hq.x, wB0.x);
                    FMA2(acc[j][3], hq.x, wB0.y);
                    FMA2(acc[j][0], hq.y, wA1.x);
                    FMA2(acc[j][1], hq.y, wA1.y);
                    FMA2(acc[j][2], hq.y, wB1.x);
                    FMA2(acc[j][3], hq.y, wB1.y);
                }
            }
            BAR3_SYNC();                       // wait: sLG/sC/sQN ready

            float2 lg0 = ((const float2*)sLG)[lane];
            float2 lg1 = ((const float2*)sLG)[32 + lane];
            float2 c0  = ((const float2*)sC)[lane];
            float2 c1  = ((const float2*)sC)[32 + lane];
            float htp0 = 0.f, htp1 = 0.f, htp2 = 0.f, htp3 = 0.f;
#pragma unroll
            for (int j = 0; j < 8; j++) {
                int rl = rbase + j;
                int rg = rank*64 + rl;
                float2 a0 = unpk(acc[j][0]);
                float2 a1 = unpk(acc[j][1]);
                float2 a2 = unpk(acc[j][2]);
                float2 a3 = unpk(acc[j][3]);
                float g0 = a0.x + a0.y + c0.x;
                float g1 = a1.x + a1.y + c0.y;
                float g2 = a2.x + a2.y + c1.x;
                float g3 = a3.x + a3.y + c1.y;
                float qe = sQE[rg], qn = sQN[rg];
                float2 h0v = ((const float2*)(sh + rl*128))[lane];
                float2 h1v = ((const float2*)(sh + rl*128))[32 + lane];
                float2 hn0, hn1;
                hn0.x = qe*lg0.x + sigm(g0)*h0v.x;
                hn0.y = qe*lg0.y + sigm(g1)*h0v.y;
                hn1.x = qe*lg1.x + sigm(g2)*h1v.x;
                hn1.y = qe*lg1.y + sigm(g3)*h1v.y;
                ((float2*)(sh + rl*128))[lane]      = hn0;
                ((float2*)(sh + rl*128))[32 + lane] = hn1;
                htp0 += qn*hn0.x; htp1 += qn*hn0.y;
                htp2 += qn*hn1.x; htp3 += qn*hn1.y;
            }
            ((float2*)(sPart + w*128))[lane]      = make_float2(htp0, htp1);
            ((float2*)(sPart + w*128))[32 + lane] = make_float2(htp2, htp3);
            BAR4_ARRIVE();                     // sPart published; roll on
        } else {
            // ================= chain warps =================
            const int ct = tid - 256;
            if (ct == 0) MBAR_EXPECT_TX(mbT, 512);   // my arrival + 512B from peer
            float ureg = 0.f;
            if (ct < 128) ureg = g_UIT[(b*NS + t)*128 + ct];
            if (ct < NQ) sQN[ct] = q_matrix[(long)e_data[b*NS + t + 1]*NQ + ct];

            // G[j] = hT @ W23 (+g23): coalesced L2 reads, deep MLP
            {
                const float* Wc = (ct < 128) ? (W2 + 49152 + ct)
                                             : (W3 + 49152 + (ct - 128));
                float acc[8];
#pragma unroll
                for (int i = 0; i < 8; i++) acc[i] = 0.f;
#pragma unroll
                for (int k = 0; k < 128; k++)
                    acc[k & 7] += sHT[k]*Wc[k*128];
                sG[ct] = ((acc[0]+acc[1]) + (acc[2]+acc[3]))
                       + ((acc[4]+acc[5]) + (acc[6]+acc[7]))
                       + g_G23[(b*NS + t)*256 + ct];
            }
            BAR_CHAIN();
            if (ct < 128) {
                float g2 = sG[ct], g3 = sG[128 + ct];
                sLG[ct] = sigm(g3) * sigm(2.f*g2);
            }
            BAR_CHAIN();

            // c = LG @ W4l ; g128 = h128 @ W4h  (k split in halves)
            {
                int f = ct & 127, half = ct >> 7;
                int k0 = half*64;
                float accc = 0.f, accg = 0.f;
#pragma unroll 16
                for (int kk = 0; kk < 64; kk++) {
                    int k = k0 + kk;
                    accc += sLG[k]*sW4l[k*128 + f];
                    accg += sh128[k]*sW4h[(k >> 1)*256 + 2*f + (k & 1)];
                }
                sCp[ct] = accc;
                sGp[ct] = accg;
            }
            BAR_CHAIN();
            float cf = 0.f, hn128 = 0.f;
            if (ct < 128) {
                cf = sCp[ct] + sCp[128 + ct] + ureg;
                sC[ct] = cf;
                float g128 = sGp[ct] + sGp[128 + ct] + cf;
                hn128 = sQE[128]*sLG[ct] + sigm(g128)*sh128[ct];
                sh128[ct] = hn128;
            }
            BAR3_ARRIVE();                     // publish sLG/sC/sQN to GEMM warps
            BAR4_SYNC();                       // wait sPart from GEMM warps

            float ownp = 0.f;
            if (ct < 128) {
#pragma unroll
                for (int ww = 0; ww < 8; ww++) ownp += sPart[ww*128 + ct];
                st_async_f32(rPHT + ct*4, ownp, rmbT);   // async-proxy, no fence
            }
            MBAR_WAIT(mbT, t & 1);
            if (ct < 128) {
                float v = __fdividef(ownp + pHT[ct] + sQN[128]*hn128,
                                     g_QS[b*NS + t + 1]);
                sHT[ct] = v;
                if (rank == 0) g_HT[(b*NS + t)*128 + ct] = v;
            }
            BAR_CHAIN();                       // sHT visible for next G-GEMV
        }
    }
}

// ============================ epilogue ======================================
__global__ void __launch_bounds__(128) lpkt_epi(
    const int* __restrict__ e_data, const float* __restrict__ E_e,
    const float* __restrict__ b5, float* __restrict__ pred)
{
    int b = blockIdx.x, f = threadIdx.x;
    __shared__ float sx[256];
    __shared__ float sr[4];
    float b5f = b5[f];
    if (blockIdx.y == 0 && f == 0) pred[b*NS] = 0.f;
    for (int tt = 0; tt < 11; tt++) {
        int t = blockIdx.y*11 + tt;
        int en = e_data[b*NS + t + 1];
        __syncthreads();
        sx[f]       = E_e[en*128 + f];
        sx[128 + f] = g_HT[(b*NS + t)*128 + f];
        __syncthreads();
        float acc = b5f;
        const float4* wp = (const float4*)(g_W5T + f*256);
        const float4* xp = (const float4*)sx;
#pragma unroll 8
        for (int k4 = 0; k4 < 64; k4++) {
            float4 wv = wp[k4], xv = xp[k4];
            acc += wv.x*xv.x + wv.y*xv.y + wv.z*xv.z + wv.w*xv.w;
        }
        float v = sigm(acc);
        v += __shfl_xor_sync(0xffffffffu, v, 16);
        v += __shfl_xor_sync(0xffffffffu, v, 8);
        v += __shfl_xor_sync(0xffffffffu, v, 4);
        v += __shfl_xor_sync(0xffffffffu, v, 2);
        v += __shfl_xor_sync(0xffffffffu, v, 1);
        if ((f & 31) == 0) sr[f >> 5] = v;
        __syncthreads();
        if (f == 0) pred[b*NS + t + 1] = (sr[0] + sr[1] + sr[2] + sr[3]) * (1.f/128.f);
    }
}

// ============================ launch ========================================
extern "C" void kernel_launch(void* const* d_in, const int* in_sizes, int n_in,
                              void* d_out, int out_size)
{
    const int*   e_data   = (const int*)  d_in[0];
    const int*   a_data   = (const int*)  d_in[1];
    const int*   it_data  = (const int*)  d_in[2];
    const int*   at_data  = (const int*)  d_in[3];
    const float* q_matrix = (const float*)d_in[4];
    const float* h0       = (const float*)d_in[5];
    const float* E_e      = (const float*)d_in[6];
    const float* E_at     = (const float*)d_in[7];
    const float* E_it     = (const float*)d_in[8];
    const float* W1       = (const float*)d_in[9];
    const float* b1       = (const float*)d_in[10];
    const float* W2       = (const float*)d_in[11];
    const float* b2       = (const float*)d_in[12];
    const float* W3       = (const float*)d_in[13];
    const float* b3       = (const float*)d_in[14];
    const float* W4       = (const float*)d_in[15];
    const float* b4       = (const float*)d_in[16];
    const float* W5       = (const float*)d_in[17];
    const float* b5       = (const float*)d_in[18];
    float* pred = (float*)d_out;

    const int SMEM_MAIN = SMEM_FLOATS * 4;   // 174,640 B
    cudaFuncSetAttribute(lpkt_main, cudaFuncAttributeMaxDynamicSharedMemorySize, SMEM_MAIN);

    prep_base<<<64, 512>>>(W1, W5, e_data, q_matrix);                       // idx 0
    prep_ALUIT<<<dim3(64, 13), 128>>>(e_data, a_data, at_data, it_data,
                                      E_e, E_at, E_it, W1, b1, W4, b4);     // idx 1
    prep_G23<<<dim3(64, 10), 256>>>(it_data, E_it, W2, b2, W3, b3);         // idx 2
    lpkt_main<<<128, 512, SMEM_MAIN>>>(e_data, q_matrix, h0, W4, W2, W3);   // idx 3
    lpkt_epi<<<dim3(64, 9), 128>>>(e_data, E_e, b5, pred);                  // idx 4
}

// round 12
// speedup vs baseline: 2.3210x; 1.0112x over previous
#include <cuda_runtime.h>
#include <cuda_bf16.h>

typedef unsigned long long u64;
typedef unsigned int u32;

#define NB 64
#define NS 100
#define NQ 129
#define DD 128

// -------------------- device scratch ---------------------------------------
__device__ __align__(16) float g_AL [NB*NS*DD];
__device__ __align__(16) float g_G23[NB*NS*2*DD];
__device__ __align__(16) float g_UIT[NB*NS*DD];
__device__ __align__(16) float g_HT [NB*NS*DD];
__device__ __align__(16) float g_W5T [DD*2*DD];   // [f][k]
__device__ __align__(16) float g_w1s [DD];
__device__ __align__(16) float g_QS  [NB*NS];

__device__ __forceinline__ float sigm(float x) {
    return __fdividef(1.f, 1.f + __expf(-x));
}
#define FMA2(d, a, bb) asm("fma.rn.f32x2 %0, %1, %2, %0;" : "+l"(d) : "l"(a), "l"(bb))
__device__ __forceinline__ float2 unpk(u64 v) {
    float2 r;
    asm("mov.b64 {%0, %1}, %2;" : "=f"(r.x), "=f"(r.y) : "l"(v));
    return r;
}
__device__ __forceinline__ u32 smem_u32(const void* p) {
    u32 a;
    asm("{ .reg .u64 t; cvta.to.shared.u64 t, %1; cvt.u32.u64 %0, t; }" : "=r"(a) : "l"(p));
    return a;
}
__device__ __forceinline__ u32 mapa_u32(u32 laddr, u32 r) {
    u32 a;
    asm("mapa.shared::cluster.u32 %0, %1, %2;" : "=r"(a) : "r"(laddr), "r"(r));
    return a;
}
__device__ __forceinline__ void st_cluster_f32(u32 raddr, float v) {
    asm volatile("st.shared::cluster.f32 [%0], %1;" :: "r"(raddr), "f"(v) : "memory");
}
__device__ __forceinline__ void st_async_f32(u32 raddr, float v, u32 rmbar) {
    asm volatile("st.async.shared::cluster.mbarrier::complete_tx::bytes.f32 [%0], %1, [%2];"
                 :: "r"(raddr), "f"(v), "r"(rmbar) : "memory");
}
#define CLUSTER_SYNC() do { \
    asm volatile("barrier.cluster.arrive.aligned;" ::: "memory"); \
    asm volatile("barrier.cluster.wait.aligned;"   ::: "memory"); \
} while (0)
#define MBARRIER_INIT(mb, c) \
    asm volatile("mbarrier.init.shared.b64 [%0], %1;" :: "r"((u32)(mb)), "r"((u32)(c)) : "memory")
#define MBAR_EXPECT_TX(mb, bytes) \
    asm volatile("mbarrier.arrive.expect_tx.shared.b64 _, [%0], %1;" \
                 :: "r"((u32)(mb)), "r"((u32)(bytes)) : "memory")
#define MBAR_WAIT(mb, par) do { \
    u32 _m = (u32)(mb), _p = (u32)(par), _d; \
    asm volatile("{ .reg .pred p; mbarrier.try_wait.parity.acquire.cta.shared::cta.b64 p, [%1], %2; selp.b32 %0, 1, 0, p; }" \
                 : "=r"(_d) : "r"(_m), "r"(_p) : "memory"); \
    if (!_d) { \
        asm volatile("{ .reg .pred P1; WL_%=: mbarrier.try_wait.parity.acquire.cta.shared::cta.b64 P1, [%0], %1, 0x989680; @P1 bra.uni WD_%=; bra.uni WL_%=; WD_%=: }" \
                     :: "r"(_m), "r"(_p) : "memory"); \
    } \
} while (0)
#define BAR_CHAIN()   asm volatile("bar.sync 1, 256;" ::: "memory")
#define BAR3_SYNC()   asm volatile("bar.sync 3, 512;" ::: "memory")
#define BAR3_ARRIVE() asm volatile("bar.arrive 3, 512;" ::: "memory")
#define BAR4_SYNC()   asm volatile("bar.sync 4, 512;" ::: "memory")
#define BAR4_ARRIVE() asm volatile("bar.arrive 4, 512;" ::: "memory")

// ============================ prep kernels (3) ==============================
__global__ void prep_base(const float* __restrict__ W1, const float* __restrict__ W5,
                          const int* __restrict__ e_data, const float* __restrict__ q_matrix)
{
    // W5T + w1s: strided item loop
    for (int idx = blockIdx.x*blockDim.x + threadIdx.x; idx < 32896;
         idx += gridDim.x*blockDim.x) {
        if (idx < 32768) {
            int f = idx >> 8, k = idx & 255;
            g_W5T[idx] = W5[k*128 + f];
        } else {
            int f = idx - 32768;
            float s = 0.f;
            for (int k = 0; k < 128; k++) s += W1[(256+k)*128 + f];
            g_w1s[f] = s;
        }
    }
    // QS: one warp per (b,t) row, shfl reduce
    int lane = threadIdx.x & 31;
    int gw = (blockIdx.x*blockDim.x + threadIdx.x) >> 5;
    int nw = (gridDim.x*blockDim.x) >> 5;
    for (int item = gw; item < NB*NS; item += nw) {
        const float* q = q_matrix + (long)e_data[item]*NQ;
        float s = 0.f;
        for (int i = lane; i < NQ; i += 32) s += q[i];
        s += __shfl_xor_sync(0xffffffffu, s, 16);
        s += __shfl_xor_sync(0xffffffffu, s, 8);
        s += __shfl_xor_sync(0xffffffffu, s, 4);
        s += __shfl_xor_sync(0xffffffffu, s, 2);
        s += __shfl_xor_sync(0xffffffffu, s, 1);
        if (lane == 0) g_QS[item] = s;
    }
}

__global__ void __launch_bounds__(128) prep_ALUIT(
    const int* __restrict__ e_data, const int* __restrict__ a_data,
    const int* __restrict__ at_data, const int* __restrict__ it_data,
    const float* __restrict__ E_e, const float* __restrict__ E_at,
    const float* __restrict__ E_it,
    const float* __restrict__ W1, const float* __restrict__ b1,
    const float* __restrict__ W4, const float* __restrict__ b4)
{
    int b = blockIdx.x, s0 = blockIdx.y*8, f = threadIdx.x;
    __shared__ float se[8][128], sa[8][128], si[8][128], av[8];
    int cnt = min(8, NS - s0);
    for (int t = 0; t < 8; t++) {
        if (t < cnt) {
            int s = s0 + t;
            se[t][f] = E_e [e_data [b*NS + s]*128 + f];
            sa[t][f] = E_at[at_data[b*NS + s]*128 + f];
            si[t][f] = E_it[it_data[b*NS + s]*128 + f];
            if (f == 0) av[t] = (float)a_data[b*NS + s];
        } else { se[t][f] = 0.f; sa[t][f] = 0.f; si[t][f] = 0.f; if (f == 0) av[t] = 0.f; }
    }
    __syncthreads();
    float w1sf = g_w1s[f], b1f = b1[f], b4f = b4[f];
    float acc[8], acu[8];
#pragma unroll
    for (int t = 0; t < 8; t++) { acc[t] = b1f + av[t]*w1sf; acu[t] = b4f; }
    for (int k = 0; k < 128; k++) {
        float w = W1[k*128 + f];
#pragma unroll
        for (int t = 0; t < 8; t++) acc[t] += se[t][k]*w;
    }
    for (int k = 0; k < 128; k++) {
        float w = W1[(128+k)*128 + f];
#pragma unroll
        for (int t = 0; t < 8; t++) acc[t] += sa[t][k]*w;
    }
    for (int k = 0; k < 128; k++) {
        float w = W4[(256+k)*128 + f];
#pragma unroll
        for (int t = 0; t < 8; t++) acu[t] += si[t][k]*w;
    }
    for (int t = 0; t < cnt; t++) {
        g_AL [(b*NS + s0 + t)*128 + f] = acc[t];
        g_UIT[(b*NS + s0 + t)*128 + f] = acu[t];
    }
}

__global__ void __launch_bounds__(256) prep_G23(
    const int* __restrict__ it_data, const float* __restrict__ E_it,
    const float* __restrict__ W2, const float* __restrict__ b2,
    const float* __restrict__ W3, const float* __restrict__ b3)
{
    int b = blockIdx.x, t0 = blockIdx.y*10;
    int T = min(10, 99 - t0);
    __shared__ float sf[10][384];
    for (int idx = threadIdx.x; idx < T*384; idx += 256) {
        int tt = idx / 384, kk = idx - tt*384;
        int t = t0 + tt;
        float v;
        if (kk < 128)       v = (t == 0) ? 0.f : g_AL[(b*NS + t - 1)*128 + kk];
        else if (kk < 256) { int it = it_data[b*NS + t]; v = E_it[it*128 + (kk-128)]; }
        else                v = g_AL[(b*NS + t)*128 + (kk-256)];
        sf[tt][kk] = v;
    }
    __syncthreads();
    int j = threadIdx.x;
    const float* Wc;
    float bias;
    if (j < 128) { Wc = W2 + j;        bias = b2[j];     }
    else         { Wc = W3 + (j-128);  bias = b3[j-128]; }
    float acc[10];
#pragma unroll
    for (int tt = 0; tt < 10; tt++) acc[tt] = bias;
    for (int k = 0; k < 384; k++) {
        float wv = Wc[k*128];
#pragma unroll
        for (int tt = 0; tt < 10; tt++) acc[tt] += sf[tt][k]*wv;
    }
    for (int tt = 0; tt < T; tt++) g_G23[(b*NS + t0 + tt)*256 + j] = acc[tt];
}

// ============================ main scan =====================================
#define OFF_SH     0        // 8192
#define OFF_SH128  8192     // 128
#define OFF_W4H    8320     // 16384 (k-pair interleaved)
#define OFF_W4L    24704    // 16384 [k][f]
#define OFF_LG     41088    // 128
#define OFF_C      41216    // 128
#define OFF_HT     41344    // 128
#define OFF_Q      41472    // 264
#define OFF_PART   41736    // 1024
#define OFF_CP     42760    // 256
#define OFF_GP     43016    // 256  (row128 gemv partials)
#define OFF_G2P    43272    // 256  (G2 partials)
#define OFF_G3P    43528    // 256  (G3 partials)
#define OFF_PHT    43784    // 128
#define OFF_MBAR   43912    // u64 mbar
#define SMEM_FLOATS 43916   // 175,664 B

__global__ void __launch_bounds__(512, 1) __cluster_dims__(2, 1, 1) lpkt_main(
    const int* __restrict__ e_data, const float* __restrict__ q_matrix,
    const float* __restrict__ h0, const float* __restrict__ W4,
    const float* __restrict__ W2, const float* __restrict__ W3)
{
    extern __shared__ float sm[];
    float* sh    = sm + OFF_SH;
    float* sh128 = sm + OFF_SH128;
    float* sW4h  = sm + OFF_W4H;
    float* sW4l  = sm + OFF_W4L;
    float* sLG   = sm + OFF_LG;
    float* sC    = sm + OFF_C;
    float* sHT   = sm + OFF_HT;
    float* sQ    = sm + OFF_Q;
    float* sPart = sm + OFF_PART;
    float* sCp   = sm + OFF_CP;
    float* sGp   = sm + OFF_GP;
    float* sG2p  = sm + OFF_G2P;
    float* sG3p  = sm + OFF_G3P;
    float* pHT   = sm + OFF_PHT;

    u32 rank;
    asm("mov.u32 %0, %%cluster_ctarank;" : "=r"(rank));
    const u32 peer = rank ^ 1u;
    const int b = blockIdx.x >> 1;
    const int tid = threadIdx.x;
    const int w = tid >> 5, lane = tid & 31;

    const u32 sb   = smem_u32(sm);
    const u32 mbT  = sb + OFF_MBAR*4;
    const u32 rmbT = mapa_u32(mbT, peer);
    const u32 rPHT = mapa_u32(sb + OFF_PHT*4, peer);

    // ---- init ----
    for (int idx = tid; idx < 16384; idx += 512) {
        int k = idx >> 7, c = idx & 127;
        sW4h[(k >> 1)*256 + 2*c + (k & 1)] = W4[idx];   // k-pair interleave
        sW4l[idx] = W4[16384 + idx];
    }
    for (int idx = tid; idx < 8192; idx += 512) sh[idx] = h0[rank*8192 + idx];
    if (tid < 128) sh128[tid] = h0[16384 + tid];
    if (tid < NQ) sQ[tid] = q_matrix[(long)e_data[b*NS]*NQ + tid];
    if (tid == 0) MBARRIER_INIT(mbT, 1);
    __syncthreads();
    CLUSTER_SYNC();

    // ---- ht0 ----
    {
        int f = tid & 127, qtr = tid >> 7;
        float acc = 0.f;
        for (int rr = 0; rr < 16; rr++) {
            int rl = qtr*16 + rr;
            acc += sQ[rank*64 + rl]*sh[rl*128 + f];
        }
        sPart[tid] = acc;
    }
    __syncthreads();
    float own0 = 0.f;
    if (tid < 128) {
        own0 = sPart[tid] + sPart[128+tid] + sPart[256+tid] + sPart[384+tid];
        st_cluster_f32(rPHT + tid*4, own0);
    }
    CLUSTER_SYNC();
    if (tid < 128)
        sHT[tid] = __fdividef(own0 + pHT[tid] + sQ[128]*sh128[tid], g_QS[b*NS]);
    __syncthreads();

    const int rbase = (w & 7)*8;

    for (int t = 0; t < 99; t++) {
        const float* sQE = sQ + (t & 1)*132;
        float*       sQN = sQ + ((t + 1) & 1)*132;

        if (w < 8) {
            // ================= GEMM warps =================
            u64 acc[8][4];
#pragma unroll
            for (int j = 0; j < 8; j++) {
                acc[j][0] = 0ull; acc[j][1] = 0ull; acc[j][2] = 0ull; acc[j][3] = 0ull;
            }
            const ulonglong2* Wq = (const ulonglong2*)sW4h;
            const ulonglong2* Hq = (const ulonglong2*)sh;
#pragma unroll 4
            for (int k4 = 0; k4 < 32; k4++) {
                ulonglong2 wA0 = Wq[(2*k4    )*64 + lane];
                ulonglong2 wB0 = Wq[(2*k4    )*64 + 32 + lane];
                ulonglong2 wA1 = Wq[(2*k4 + 1)*64 + lane];
                ulonglong2 wB1 = Wq[(2*k4 + 1)*64 + 32 + lane];
#pragma unroll
                for (int j = 0; j < 8; j++) {
                    ulonglong2 hq = Hq[(rbase + j)*32 + k4];
                    FMA2(acc[j][0], hq.x, wA0.x);
                    FMA2(acc[j][1], hq.x, wA0.y);
                    FMA2(acc[j][2], hq.x, wB0.x);
                    FMA2(acc[j][3], hq.x, wB0.y);
                    FMA2(acc[j][0], hq.y, wA1.x);
                    FMA2(acc[j][1], hq.y, wA1.y);
                    FMA2(acc[j][2], hq.y, wB1.x);
                    FMA2(acc[j][3], hq.y, wB1.y);
                }
            }
            BAR3_SYNC();                       // wait: sLG/sC/sQN ready

            float2 lg0 = ((const float2*)sLG)[lane];
            float2 lg1 = ((const float2*)sLG)[32 + lane];
            float2 c0  = ((const float2*)sC)[lane];
            float2 c1  = ((const float2*)sC)[32 + lane];
            float htp0 = 0.f, htp1 = 0.f, htp2 = 0.f, htp3 = 0.f;
#pragma unroll
            for (int j = 0; j < 8; j++) {
                int rl = rbase + j;
                int rg = rank*64 + rl;
                float2 a0 = unpk(acc[j][0]);
                float2 a1 = unpk(acc[j][1]);
                float2 a2 = unpk(acc[j][2]);
                float2 a3 = unpk(acc[j][3]);
                float g0 = a0.x + a0.y + c0.x;
                float g1 = a1.x + a1.y + c0.y;
                float g2 = a2.x + a2.y + c1.x;
                float g3 = a3.x + a3.y + c1.y;
                float qe = sQE[rg], qn = sQN[rg];
                float2 h0v = ((const float2*)(sh + rl*128))[lane];
                float2 h1v = ((const float2*)(sh + rl*128))[32 + lane];
                float2 hn0, hn1;
                hn0.x = qe*lg0.x + sigm(g0)*h0v.x;
                hn0.y = qe*lg0.y + sigm(g1)*h0v.y;
                hn1.x = qe*lg1.x + sigm(g2)*h1v.x;
                hn1.y = qe*lg1.y + sigm(g3)*h1v.y;
                ((float2*)(sh + rl*128))[lane]      = hn0;
                ((float2*)(sh + rl*128))[32 + lane] = hn1;
                htp0 += qn*hn0.x; htp1 += qn*hn0.y;
                htp2 += qn*hn1.x; htp3 += qn*hn1.y;
            }
            ((float2*)(sPart + w*128))[lane]      = make_float2(htp0, htp1);
            ((float2*)(sPart + w*128))[32 + lane] = make_float2(htp2, htp3);
            BAR4_ARRIVE();                     // sPart published; roll on
        } else {
            // ================= chain warps =================
            const int ct = tid - 256;
            if (ct == 0) MBAR_EXPECT_TX(mbT, 512);
            float ureg = 0.f;
            if (ct < 128) ureg = g_UIT[(b*NS + t)*128 + ct];
            if (ct < NQ) sQN[ct] = q_matrix[(long)e_data[b*NS + t + 1]*NQ + ct];

            // G partials: all 256 threads, k-split in halves, both W2 & W3 dots
            {
                int j = ct & 127, kk0 = (ct >> 7)*64;
                const float* W2c = W2 + (384 + kk0)*128 + j;
                const float* W3c = W3 + (384 + kk0)*128 + j;
                const float* hpt = sHT + kk0;
                float a2[4] = {0.f, 0.f, 0.f, 0.f};
                float a3[4] = {0.f, 0.f, 0.f, 0.f};
#pragma unroll 8
                for (int kk = 0; kk < 64; kk++) {
                    float hv = hpt[kk];
                    a2[kk & 3] += hv*W2c[kk*128];
                    a3[kk & 3] += hv*W3c[kk*128];
                }
                sG2p[ct] = (a2[0] + a2[1]) + (a2[2] + a2[3]);
                sG3p[ct] = (a3[0] + a3[1]) + (a3[2] + a3[3]);
            }
            BAR_CHAIN();
            if (ct < 128) {
                const float* gb = g_G23 + (b*NS + t)*256;
                float g2 = sG2p[ct] + sG2p[128 + ct] + gb[ct];
                float g3 = sG3p[ct] + sG3p[128 + ct] + gb[128 + ct];
                sLG[ct] = sigm(g3) * sigm(2.f*g2);
            }
            BAR_CHAIN();

            // c = LG @ W4l ; g128 = h128 @ W4h  (k split in halves)
            {
                int f = ct & 127, half = ct >> 7;
                int k0 = half*64;
                float accc = 0.f, accg = 0.f;
#pragma unroll 16
                for (int kk = 0; kk < 64; kk++) {
                    int k = k0 + kk;
                    accc += sLG[k]*sW4l[k*128 + f];
                    accg += sh128[k]*sW4h[(k >> 1)*256 + 2*f + (k & 1)];
                }
                sCp[ct] = accc;
                sGp[ct] = accg;
            }
            BAR_CHAIN();
            float cf = 0.f, hn128 = 0.f;
            if (ct < 128) {
                cf = sCp[ct] + sCp[128 + ct] + ureg;
                sC[ct] = cf;
                float g128 = sGp[ct] + sGp[128 + ct] + cf;
                hn128 = sQE[128]*sLG[ct] + sigm(g128)*sh128[ct];
                sh128[ct] = hn128;
            }
            BAR3_ARRIVE();                     // publish sLG/sC/sQN
            BAR4_SYNC();                       // wait sPart

            float ownp = 0.f;
            if (ct < 128) {
#pragma unroll
                for (int ww = 0; ww < 8; ww++) ownp += sPart[ww*128 + ct];
                st_async_f32(rPHT + ct*4, ownp, rmbT);
            }
            MBAR_WAIT(mbT, t & 1);
            if (ct < 128) {
                float v = __fdividef(ownp + pHT[ct] + sQN[128]*hn128,
                                     g_QS[b*NS + t + 1]);
                sHT[ct] = v;
                if (rank == 0) g_HT[(b*NS + t)*128 + ct] = v;
            }
            BAR_CHAIN();                       // sHT visible for next G-GEMV
        }
    }
}

// ============================ epilogue ======================================
__global__ void __launch_bounds__(128) lpkt_epi(
    const int* __restrict__ e_data, const float* __restrict__ E_e,
    const float* __restrict__ b5, float* __restrict__ pred)
{
    int b = blockIdx.x, f = threadIdx.x;
    __shared__ float sx[256];
    __shared__ float sr[4];
    float b5f = b5[f];
    if (blockIdx.y == 0 && f == 0) pred[b*NS] = 0.f;
    for (int tt = 0; tt < 11; tt++) {
        int t = blockIdx.y*11 + tt;
        int en = e_data[b*NS + t + 1];
        __syncthreads();
        sx[f]       = E_e[en*128 + f];
        sx[128 + f] = g_HT[(b*NS + t)*128 + f];
        __syncthreads();
        float acc = b5f;
        const float4* wp = (const float4*)(g_W5T + f*256);
        const float4* xp = (const float4*)sx;
#pragma unroll 8
        for (int k4 = 0; k4 < 64; k4++) {
            float4 wv = wp[k4], xv = xp[k4];
            acc += wv.x*xv.x + wv.y*xv.y + wv.z*xv.z + wv.w*xv.w;
        }
        float v = sigm(acc);
        v += __shfl_xor_sync(0xffffffffu, v, 16);
        v += __shfl_xor_sync(0xffffffffu, v, 8);
        v += __shfl_xor_sync(0xffffffffu, v, 4);
        v += __shfl_xor_sync(0xffffffffu, v, 2);
        v += __shfl_xor_sync(0xffffffffu, v, 1);
        if ((f & 31) == 0) sr[f >> 5] = v;
        __syncthreads();
        if (f == 0) pred[b*NS + t + 1] = (sr[0] + sr[1] + sr[2] + sr[3]) * (1.f/128.f);
    }
}

// ============================ launch ========================================
extern "C" void kernel_launch(void* const* d_in, const int* in_sizes, int n_in,
                              void* d_out, int out_size)
{
    const int*   e_data   = (const int*)  d_in[0];
    const int*   a_data   = (const int*)  d_in[1];
    const int*   it_data  = (const int*)  d_in[2];
    const int*   at_data  = (const int*)  d_in[3];
    const float* q_matrix = (const float*)d_in[4];
    const float* h0       = (const float*)d_in[5];
    const float* E_e      = (const float*)d_in[6];
    const float* E_at     = (const float*)d_in[7];
    const float* E_it     = (const float*)d_in[8];
    const float* W1       = (const float*)d_in[9];
    const float* b1       = (const float*)d_in[10];
    const float* W2       = (const float*)d_in[11];
    const float* b2       = (const float*)d_in[12];
    const float* W3       = (const float*)d_in[13];
    const float* b3       = (const float*)d_in[14];
    const float* W4       = (const float*)d_in[15];
    const float* b4       = (const float*)d_in[16];
    const float* W5       = (const float*)d_in[17];
    const float* b5       = (const float*)d_in[18];
    float* pred = (float*)d_out;

    const int SMEM_MAIN = SMEM_FLOATS * 4;   // 175,664 B
    cudaFuncSetAttribute(lpkt_main, cudaFuncAttributeMaxDynamicSharedMemorySize, SMEM_MAIN);

    prep_base<<<64, 512>>>(W1, W5, e_data, q_matrix);                       // idx 0
    prep_ALUIT<<<dim3(64, 13), 128>>>(e_data, a_data, at_data, it_data,
                                      E_e, E_at, E_it, W1, b1, W4, b4);     // idx 1
    prep_G23<<<dim3(64, 10), 256>>>(it_data, E_it, W2, b2, W3, b3);         // idx 2
    lpkt_main<<<128, 512, SMEM_MAIN>>>(e_data, q_matrix, h0, W4, W2, W3);   // idx 3
    lpkt_epi<<<dim3(64, 9), 128>>>(e_data, E_e, b5, pred);                  // idx 4
}